// round 14
// baseline (speedup 1.0000x reference)
#include <cuda_runtime.h>
#include <cuda_bf16.h>
#include <mma.h>
#include <math.h>

using namespace nvcuda;

#define BB 4
#define LL 2048
#define DD 512
#define BL (BB*LL)

#define NEGV     (-10000.0f)
#define INV_TAU  (1.0f/1.5f)
#define INV_TAU_SS 0.8f
#define LOG2E    1.4426950408889634f
#define LN2      0.6931471805599453f

#define CK 1552   // content K

// ---------------- scratch (static device memory) ----------------
__device__ __nv_bfloat16 g_attn[(size_t)BL * LL];     // 33.5 MB
__device__ __nv_bfloat16 g_Hbf[(size_t)BL * DD];
__device__ float g_ctx[(size_t)BL * DD];
__device__ float g_content[(size_t)BL * CK];
__device__ __nv_bfloat16 g_cw1hi[128*CK], g_cw1lo[128*CK];
__device__ __nv_bfloat16 g_kw1hi[256*496];            // padded N 248->256 (2-term)
__device__ float g_kb1p[256];
__device__ float g_curv_h1[(size_t)BL * 248];
__device__ float g_curv[(size_t)BL * 16];
__device__ float g_cont_h1[(size_t)BL * 128];
__device__ float g_statsin[(size_t)BL * 21];
__device__ float g_mrg[(size_t)BL * 96];
__device__ float g_pm[BL], g_mpp[BL], g_unp[BL], g_pen[BL], g_lm[BL], g_dm[BL];
__device__ int   g_ti[BL*3];
__device__ float g_twk[BL*3];
__device__ int   g_nb[BB];
__device__ unsigned char g_mask[BL];

// ---------------- helpers ----------------
__device__ inline float nan_fix(float x) {
    if (isnan(x)) return 0.0f;
    if (isinf(x)) return x > 0.0f ? 1.0f : 0.0f;
    return x;
}

__device__ inline float gelu_exact(float x) {
    return 0.5f * x * (1.0f + erff(x * 0.70710678118654752f));
}

__device__ inline unsigned ord_pack(float x) {
    unsigned u = __float_as_uint(x);
    return u ^ ((unsigned)(((int)u) >> 31) | 0x80000000u);
}
__device__ inline float ord_unpack(unsigned m) {
    unsigned u = (m & 0x80000000u) ? (m ^ 0x80000000u) : ~m;
    return __uint_as_float(u);
}

__device__ inline void cp_async16(void* smem_dst, const void* gmem_src) {
    unsigned sa = (unsigned)__cvta_generic_to_shared(smem_dst);
    asm volatile("cp.async.cg.shared.global [%0], [%1], 16;\n" :: "r"(sa), "l"(gmem_src));
}

// ---------------- H -> bf16 + all weight conversions (also zeroes g_nb) ----------------
__global__ void convert_all_kernel(const float* __restrict__ H,
                                   const float* __restrict__ cw1,
                                   const float* __restrict__ kw1,
                                   const float* __restrict__ kb1) {
    int idx = blockIdx.x * blockDim.x + threadIdx.x;
    if (blockIdx.x == 0 && threadIdx.x < BB) g_nb[threadIdx.x] = 0;

    int nH = BL * DD / 4;
    int n1 = 128 * CK;
    int n2 = 256 * 496;
    int ntot = nH + n1 + n2 + 256;

    for (; idx < ntot; idx += gridDim.x * blockDim.x) {
        if (idx < nH) {
            float4 v = ((const float4*)H)[idx];
            __nv_bfloat162 a = __floats2bfloat162_rn(v.x, v.y);
            __nv_bfloat162 b = __floats2bfloat162_rn(v.z, v.w);
            ((__nv_bfloat162*)g_Hbf)[idx*2]   = a;
            ((__nv_bfloat162*)g_Hbf)[idx*2+1] = b;
        } else if (idx < nH + n1) {
            int q = idx - nH;
            float x = cw1[q];
            __nv_bfloat16 h = __float2bfloat16(x);
            g_cw1hi[q] = h;
            g_cw1lo[q] = __float2bfloat16(x - __bfloat162float(h));
        } else if (idx < nH + n1 + n2) {
            int q = idx - nH - n1;
            float x = (q < 248*496) ? kw1[q] : 0.0f;
            g_kw1hi[q] = __float2bfloat16(x);
        } else {
            int q = idx - nH - n1 - n2;
            g_kb1p[q] = (q < 248) ? kb1[q] : 0.0f;
        }
    }
}

// ---------------- mask expand (dtype detect inline) ----------------
__global__ void mask_expand_kernel(const void* M) {
    int idx = blockIdx.x * blockDim.x + threadIdx.x;
    if (idx >= BL) return;
    unsigned int w = *(const unsigned int*)M;
    int mode;
    if      (w == 0x01010101u) mode = 0;
    else if (w == 0x3F800000u) mode = 2;
    else if (w == 0x3F803F80u) mode = 3;
    else                       mode = 1;
    unsigned char v;
    if      (mode == 0) v = ((const unsigned char*)M)[idx] != 0;
    else if (mode == 1) v = ((const int*)M)[idx] != 0;
    else if (mode == 2) v = ((const float*)M)[idx] != 0.0f;
    else                v = ((const unsigned short*)M)[idx] != 0;
    g_mask[idx] = v;
    unsigned int ball = __ballot_sync(0xffffffffu, v != 0);
    if ((idx & 31) == 0) atomicAdd(&g_nb[idx >> 11], __popc(ball));
}

// ---------------- fused row stats v3 (REDUX top-3), per-batch ----------------
__global__ __launch_bounds__(256) void row_stats_kernel(const float* __restrict__ PL, int r0base)
{
    __shared__ unsigned swm[8];
    __shared__ unsigned swi[8];
    __shared__ float redf[8*3];
    __shared__ float bc[4];

    int r = r0base + blockIdx.x;
    int b = r >> 11;
    int i = r & (LL - 1);
    int tid = threadIdx.x;
    int lane = tid & 31, wid = tid >> 5;

    const float* row = PL + (size_t)r * LL;
    const unsigned char* mrow = g_mask + (size_t)b * LL;
    int Nb = g_nb[b];
    bool allv = (Nb == LL);
    bool mi = mrow[i] != 0;

    int j0 = tid * 8;
    float x[8];
    *(float4*)&x[0] = *(const float4*)&row[j0];
    *(float4*)&x[4] = *(const float4*)&row[j0 + 4];

    if (mi && allv) {
        if (i >= j0 && i < j0 + 8) x[i - j0] = NEGV;
    } else if (!mi) {
        #pragma unroll
        for (int t = 0; t < 8; t++) x[t] = NEGV;
    } else {
        #pragma unroll
        for (int t = 0; t < 8; t++) {
            int j = j0 + t;
            if (j == i || !mrow[j]) x[t] = NEGV;
        }
    }

    unsigned ou[8];
    #pragma unroll
    for (int t = 0; t < 8; t++) ou[t] = ord_pack(x[t]);

    unsigned selv[3], seli[3];
    #pragma unroll
    for (int k3 = 0; k3 < 3; k3++) {
        unsigned tm = ou[0];
        #pragma unroll
        for (int t = 1; t < 8; t++) tm = max(tm, ou[t]);
        unsigned wm = __reduce_max_sync(0xffffffffu, tm);
        if (lane == 0) swm[wid] = wm;
        __syncthreads();
        unsigned M = swm[0];
        #pragma unroll
        for (int w = 1; w < 8; w++) M = max(M, swm[w]);

        unsigned mi_idx = 0xFFFFFFFFu;
        #pragma unroll
        for (int t = 0; t < 8; t++)
            if (ou[t] == M) mi_idx = min(mi_idx, (unsigned)(j0 + t));
        unsigned wmi = __reduce_min_sync(0xffffffffu, mi_idx);
        if (lane == 0) swi[wid] = wmi;
        __syncthreads();
        unsigned I = swi[0];
        #pragma unroll
        for (int w = 1; w < 8; w++) I = min(I, swi[w]);

        selv[k3] = M; seli[k3] = I;
        if (I >= (unsigned)j0 && I < (unsigned)(j0 + 8)) ou[I - j0] = 0u;
    }

    float m = ord_unpack(selv[0]);
    float mx2 = m * (INV_TAU * LOG2E);
    float enm = exp2f(-mx2);

    float S = 0.0f, T2 = 0.0f, G = 0.0f;
    #pragma unroll
    for (int t = 0; t < 8; t++) {
        float d2 = fmaf(x[t], INV_TAU * LOG2E, -mx2);
        float e = exp2f(d2);
        S += e;
        T2 = fmaf(e, d2, T2);
        float sg = __fdividef(e, e + enm);
        G += sg;
    }
    #pragma unroll
    for (int off = 16; off >= 1; off >>= 1) {
        S  += __shfl_down_sync(0xffffffffu, S, off);
        T2 += __shfl_down_sync(0xffffffffu, T2, off);
        G  += __shfl_down_sync(0xffffffffu, G, off);
    }
    if (lane == 0) { redf[wid*3+0] = S; redf[wid*3+1] = T2; redf[wid*3+2] = G; }
    __syncthreads();
    if (wid == 0) {
        float s = 0, t2 = 0, g = 0;
        if (lane < 8) { s = redf[lane*3+0]; t2 = redf[lane*3+1]; g = redf[lane*3+2]; }
        #pragma unroll
        for (int off = 4; off >= 1; off >>= 1) {
            s  += __shfl_down_sync(0xffffffffu, s, off);
            t2 += __shfl_down_sync(0xffffffffu, t2, off);
            g  += __shfl_down_sync(0xffffffffu, g, off);
        }
        int jw = i - 8 + lane;
        float gl = 0.0f;
        if (lane < 17 && jw >= 0 && jw < LL) {
            float xw = row[jw];
            bool valid = mi && (jw != i) && (allv || mrow[jw]);
            if (!valid) xw = NEGV;
            float d2 = fmaf(xw, INV_TAU * LOG2E, -mx2);
            float e = exp2f(d2);
            gl = __fdividef(e, e + enm);
        }
        #pragma unroll
        for (int off = 16; off >= 1; off >>= 1)
            gl += __shfl_down_sync(0xffffffffu, gl, off);
        if (lane == 0) { bc[0] = s; bc[1] = t2; bc[2] = g; bc[3] = gl; }
    }
    __syncthreads();

    float St = bc[0];
    float invS = __fdividef(1.0f, St);

    __nv_bfloat162 ob[4];
    #pragma unroll
    for (int p = 0; p < 4; p++) {
        float e0 = exp2f(fmaf(x[2*p],   INV_TAU * LOG2E, -mx2));
        float e1 = exp2f(fmaf(x[2*p+1], INV_TAU * LOG2E, -mx2));
        ob[p] = __floats2bfloat162_rn(e0 * invS, e1 * invS);
    }
    *(uint4*)&g_attn[(size_t)r * LL + j0] = *(uint4*)ob;

    if (tid == 0) {
        float Tt = bc[1] * LN2;
        float Gt = bc[2];
        float Glt = bc[3];

        int lo = i - 8 < 0 ? 0 : i - 8;
        int hi = i + 8 > LL-1 ? LL-1 : i + 8;
        float wcount;
        if (allv) wcount = (float)(hi - lo + 1);
        else { int c = 0; for (int j = lo; j <= hi; j++) c += mrow[j]; wcount = (float)c; }
        float nvalid  = mi ? (float)(Nb - 1) : 0.0f;
        float nlocal  = mi ? (wcount - 1.0f) : 0.0f;
        float ndistal = nvalid - nlocal;

        float entropy = logf(St) - Tt / St;
        float maxpp = __fdividef(1.0f, 1.0f + enm);
        float pen = entropy / fmaxf(logf(fmaxf(nvalid, 1.0f)), 1e-4f);
        pen = fminf(fmaxf(pen, 0.0f), 1.0f);

        g_pm[r]  = __fdividef(Gt, fmaxf(nvalid, 1.0f));
        g_mpp[r] = maxpp;
        g_unp[r] = 1.0f - maxpp;
        g_pen[r] = nan_fix(pen);
        g_lm[r]  = __fdividef(Glt, fmaxf(nlocal, 1.0f));
        g_dm[r]  = __fdividef(Gt - Glt, fmaxf(ndistal, 1.0f));

        float tvv[3] = {ord_unpack(selv[0]), ord_unpack(selv[1]), ord_unpack(selv[2])};
        float mt = (tvv[0] > -9000.0f) ? tvv[0] : NEGV;
        float a[3]; float ssum = 0.0f;
        #pragma unroll
        for (int k = 0; k < 3; k++) {
            bool val = tvv[k] > -9000.0f;
            a[k] = val ? __expf((tvv[k] - mt) * INV_TAU) : 0.0f;
            ssum += a[k];
        }
        float inv = __fdividef(1.0f, fmaxf(ssum, 1e-8f));
        #pragma unroll
        for (int k = 0; k < 3; k++) {
            g_twk[r*3+k] = a[k] * inv;
            g_ti[r*3+k]  = (int)seli[k];
        }
    }
}

// ---------------- ctx = attn @ H (wmma, 3-stage, R9 scheme), per-batch ----------------
#define CTX_STAGE_A (128*40)
#define CTX_STAGE_B (32*136)
#define CTX_STAGE_ELEMS (CTX_STAGE_A + CTX_STAGE_B)
#define CTX_SMEM_BYTES (3 * CTX_STAGE_ELEMS * 2)

__global__ __launch_bounds__(256, 2) void ctx_gemm_kernel(int b) {
    extern __shared__ __align__(16) __nv_bfloat16 smem_ctx[];
    __nv_bfloat16* As[3];
    __nv_bfloat16* Bs[3];
    #pragma unroll
    for (int s = 0; s < 3; s++) {
        As[s] = smem_ctx + s * CTX_STAGE_ELEMS;
        Bs[s] = As[s] + CTX_STAGE_A;
    }

    int m0 = blockIdx.x * 128;
    int n0 = blockIdx.y * 128;
    const __nv_bfloat16* A  = g_attn + (size_t)b * LL * LL;
    const __nv_bfloat16* Bm = g_Hbf  + (size_t)b * LL * DD;
    float* C = g_ctx + (size_t)b * LL * DD;

    int tid = threadIdx.x;
    int wid = tid >> 5;
    int wm = wid & 3;
    int wn = wid >> 2;

    wmma::fragment<wmma::accumulator, 16, 16, 16, float> acc[2][4];
    #pragma unroll
    for (int x = 0; x < 2; x++)
        #pragma unroll
        for (int y = 0; y < 4; y++)
            wmma::fill_fragment(acc[x][y], 0.0f);

    auto load_stage = [&](int st, int k0) {
        #pragma unroll
        for (int it = 0; it < 2; it++) {
            int q = tid + it * 256;
            int rowA = q >> 2, c4 = q & 3;
            cp_async16(&As[st][rowA * 40 + c4 * 8],
                       &A[(size_t)(m0 + rowA) * LL + k0 + c4 * 8]);
            int rowB = q >> 4, c16 = q & 15;
            cp_async16(&Bs[st][rowB * 136 + c16 * 8],
                       &Bm[(size_t)(k0 + rowB) * DD + n0 + c16 * 8]);
        }
        asm volatile("cp.async.commit_group;\n" ::: "memory");
    };

    load_stage(0, 0);
    load_stage(1, 32);
    load_stage(2, 64);

    for (int c = 0; c < 64; c++) {
        int st = c % 3;
        if (c < 62) asm volatile("cp.async.wait_group 2;\n" ::: "memory");
        else        asm volatile("cp.async.wait_group 0;\n" ::: "memory");
        __syncthreads();
        #pragma unroll
        for (int kk = 0; kk < 32; kk += 16) {
            wmma::fragment<wmma::matrix_a, 16, 16, 16, __nv_bfloat16, wmma::row_major> af[2];
            wmma::fragment<wmma::matrix_b, 16, 16, 16, __nv_bfloat16, wmma::row_major> bf[4];
            #pragma unroll
            for (int x = 0; x < 2; x++)
                wmma::load_matrix_sync(af[x], &As[st][(wm*32 + x*16) * 40 + kk], 40);
            #pragma unroll
            for (int y = 0; y < 4; y++)
                wmma::load_matrix_sync(bf[y], &Bs[st][kk * 136 + wn*64 + y*16], 136);
            #pragma unroll
            for (int x = 0; x < 2; x++)
                #pragma unroll
                for (int y = 0; y < 4; y++)
                    wmma::mma_sync(acc[x][y], af[x], bf[y], acc[x][y]);
        }
        __syncthreads();
        if (c + 3 < 64) load_stage(st, (c + 3) * 32);
    }

    #pragma unroll
    for (int x = 0; x < 2; x++)
        #pragma unroll
        for (int y = 0; y < 4; y++)
            wmma::store_matrix_sync(
                C + (size_t)(m0 + wm*32 + x*16) * DD + n0 + wn*64 + y*16,
                acc[x][y], DD, wmma::mem_row_major);
}

// ---------------- hi/lo bf16 tensor-core GEMM, fp32 A split in-kernel ----------------
template<int ACT, int PREC>
__global__ __launch_bounds__(256) void wmma_hilo_gemm_f32A(
    const float* __restrict__ A,
    const __nv_bfloat16* __restrict__ Whi, const __nv_bfloat16* __restrict__ Wlo,
    const float* __restrict__ bias, float* __restrict__ C,
    int K, int Nout, int ldc)
{
    __shared__ __align__(16) char sraw[35840];
    __nv_bfloat16* sAhi = (__nv_bfloat16*)sraw;
    __nv_bfloat16* sAlo = sAhi + 128*40;
    __nv_bfloat16* sWhi = sAlo + 128*40;
    __nv_bfloat16* sWlo = sWhi + 64*40;
    float* stage = (float*)sraw;

    int m0 = blockIdx.x * 128;
    int n0 = blockIdx.y * 64;
    int tid = threadIdx.x, wid = tid >> 5;
    int wm = wid & 3, wn = wid >> 2;

    wmma::fragment<wmma::accumulator, 16, 16, 16, float> acc[2][2];
    #pragma unroll
    for (int x = 0; x < 2; x++)
        #pragma unroll
        for (int y = 0; y < 2; y++)
            wmma::fill_fragment(acc[x][y], 0.0f);

    int Kpad = (K + 31) & ~31;
    for (int k0 = 0; k0 < Kpad; k0 += 32) {
        #pragma unroll
        for (int it = 0; it < 4; it++) {
            int q = tid + it * 256;
            int rowA = q >> 3, c = q & 7;
            int kidx = k0 + c * 4;
            float4 v = make_float4(0.f, 0.f, 0.f, 0.f);
            if (kidx < K)
                v = *(const float4*)&A[(size_t)(m0 + rowA) * K + kidx];
            float xs[4] = {v.x, v.y, v.z, v.w};
            #pragma unroll
            for (int u = 0; u < 4; u++) {
                __nv_bfloat16 h = __float2bfloat16(xs[u]);
                sAhi[rowA*40 + c*4 + u] = h;
                sAlo[rowA*40 + c*4 + u] = __float2bfloat16(xs[u] - __bfloat162float(h));
            }
        }
        {
            int rowN = tid >> 2, c4 = tid & 3;
            int kidx = k0 + c4 * 8;
            uint4 vh = make_uint4(0,0,0,0), vl = make_uint4(0,0,0,0);
            if (kidx < K) {
                vh = *(const uint4*)&Whi[(size_t)(n0 + rowN) * K + kidx];
                if (PREC) vl = *(const uint4*)&Wlo[(size_t)(n0 + rowN) * K + kidx];
            }
            *(uint4*)&sWhi[rowN * 40 + c4 * 8] = vh;
            if (PREC) *(uint4*)&sWlo[rowN * 40 + c4 * 8] = vl;
        }
        __syncthreads();
        #pragma unroll
        for (int kk = 0; kk < 32; kk += 16) {
            wmma::fragment<wmma::matrix_a, 16, 16, 16, __nv_bfloat16, wmma::row_major> ah[2], al[2];
            wmma::fragment<wmma::matrix_b, 16, 16, 16, __nv_bfloat16, wmma::col_major> bh[2], bl[2];
            #pragma unroll
            for (int x = 0; x < 2; x++) {
                wmma::load_matrix_sync(ah[x], &sAhi[(wm*32 + x*16) * 40 + kk], 40);
                wmma::load_matrix_sync(al[x], &sAlo[(wm*32 + x*16) * 40 + kk], 40);
            }
            #pragma unroll
            for (int y = 0; y < 2; y++) {
                wmma::load_matrix_sync(bh[y], &sWhi[(wn*32 + y*16) * 40 + kk], 40);
                if (PREC) wmma::load_matrix_sync(bl[y], &sWlo[(wn*32 + y*16) * 40 + kk], 40);
            }
            #pragma unroll
            for (int x = 0; x < 2; x++)
                #pragma unroll
                for (int y = 0; y < 2; y++) {
                    wmma::mma_sync(acc[x][y], ah[x], bh[y], acc[x][y]);
                    if (PREC) wmma::mma_sync(acc[x][y], ah[x], bl[y], acc[x][y]);
                    wmma::mma_sync(acc[x][y], al[x], bh[y], acc[x][y]);
                }
        }
        __syncthreads();
    }

    #pragma unroll
    for (int x = 0; x < 2; x++)
        #pragma unroll
        for (int y = 0; y < 2; y++)
            wmma::store_matrix_sync(&stage[(wm*32 + x*16) * 68 + wn*32 + y*16],
                                    acc[x][y], 68, wmma::mem_row_major);
    __syncthreads();
    #pragma unroll
    for (int t = 0; t < 32; t++) {
        int q = tid + t * 256;
        int rowm = q >> 6, col = q & 63;
        int n = n0 + col;
        if (n < Nout) {
            float c = stage[rowm * 68 + col] + bias[n];
            if (ACT == 1) c = gelu_exact(c);
            C[(size_t)(m0 + rowm) * ldc + n] = c;
        }
    }
}

// ---------------- SIMT fp32 GEMM (small layers) ----------------
template<int ACT>
__global__ __launch_bounds__(256) void simt_gemm(
    const float* __restrict__ A, const float* __restrict__ W,
    const float* __restrict__ bias, float* __restrict__ C,
    int M, int N, int K, int ldc)
{
    __shared__ __align__(16) float As[16][68];
    __shared__ __align__(16) float Ws[16][68];
    int m0 = blockIdx.x * 64;
    int n0 = blockIdx.y * 64;
    int tid = threadIdx.x;
    int tr = tid & 15, tc = tid >> 4;

    float acc[4][4] = {};

    for (int k0 = 0; k0 < K; k0 += 16) {
        #pragma unroll
        for (int it = 0; it < 4; it++) {
            int q = tid + it * 256;
            int m = q >> 4, k = q & 15;
            As[k][m] = (k0 + k < K) ? A[(size_t)(m0 + m) * K + k0 + k] : 0.0f;
            int n = m;
            Ws[k][n] = (n0 + n < N && k0 + k < K) ? W[(size_t)(n0 + n) * K + k0 + k] : 0.0f;
        }
        __syncthreads();
        #pragma unroll
        for (int kk = 0; kk < 16; kk++) {
            float4 av = *(const float4*)&As[kk][tr * 4];
            float4 wv = *(const float4*)&Ws[kk][tc * 4];
            float a4[4] = {av.x, av.y, av.z, av.w};
            float w4[4] = {wv.x, wv.y, wv.z, wv.w};
            #pragma unroll
            for (int x = 0; x < 4; x++)
                #pragma unroll
                for (int y = 0; y < 4; y++)
                    acc[x][y] += a4[x] * w4[y];
        }
        __syncthreads();
    }

    #pragma unroll
    for (int x = 0; x < 4; x++) {
        int m = m0 + tr * 4 + x;
        #pragma unroll
        for (int y = 0; y < 4; y++) {
            int n = n0 + tc * 4 + y;
            if (n < N) {
                float c = acc[x][y] + bias[n];
                if (ACT == 1) c = gelu_exact(c);
                C[(size_t)m * ldc + n] = c;
            }
        }
    }
}

// ---------------- stats finalize + layernorm + ss ----------------
__global__ void stats_finalize_kernel(
    const float* __restrict__ SS,
    const float* __restrict__ sslp_w, const float* __restrict__ sslp_b,
    const float* __restrict__ ln_g, const float* __restrict__ ln_b,
    float* __restrict__ out, int write_stats)
{
    int r = blockIdx.x * blockDim.x + threadIdx.x;
    if (r >= BL) return;
    int b = r >> 11;
    int i = r & (LL - 1);
    const unsigned char* mrow = g_mask + (size_t)b * LL;
    float mf = mrow[i] ? 1.0f : 0.0f;

    const float* s = SS + (size_t)r * 3;
    float s0 = s[0], s1 = s[1], s2 = s[2];
    float t0 = s0 * INV_TAU_SS, t1 = s1 * INV_TAU_SS, t2 = s2 * INV_TAU_SS;
    float mss = fmaxf(t0, fmaxf(t1, t2));
    float e0 = __expf(t0 - mss), e1 = __expf(t1 - mss), e2 = __expf(t2 - mss);
    float es = e0 + e1 + e2;
    float p0 = e0 / es, p1 = e1 / es, p2 = e2 / es;
    float ssent = -(p0 * logf(p0 + 1e-8f) + p1 * logf(p1 + 1e-8f) + p2 * logf(p2 + 1e-8f));

    float sx3 = 0, sm3 = 0, sx7 = 0, sm7 = 0, se7 = 0;
    for (int d = -5; d <= 5; d++) {
        int j = i + d;
        if (j < 0 || j >= LL) continue;
        float mfj = mrow[j] ? 1.0f : 0.0f;
        int rj = b * LL + j;
        float u = g_unp[rj] * mfj;
        float p = g_pen[rj] * mfj;
        if (d >= -2 && d <= 2) { sx3 += u; sm3 += mfj; }
        sx7 += u; sm7 += mfj; se7 += p;
    }
    float w3 = sx3 / fmaxf(sm3, 1.0f);
    float w7 = sx7 / fmaxf(sm7, 1.0f);
    float e7 = se7 / fmaxf(sm7, 1.0f);

    float st[10];
    st[0] = g_pm[r]; st[1] = g_mpp[r]; st[2] = g_unp[r]; st[3] = g_pen[r];
    st[4] = ssent;   st[5] = g_lm[r];  st[6] = g_dm[r];
    st[7] = w3; st[8] = w7; st[9] = e7;
    #pragma unroll
    for (int c = 0; c < 10; c++) st[c] = nan_fix(st[c] * mf);

    if (write_stats) {
        float* os = out + (size_t)BL * 64 + (size_t)r * 10;
        #pragma unroll
        for (int c = 0; c < 10; c++) os[c] = st[c];
    }

    float mean = 0;
    #pragma unroll
    for (int c = 0; c < 10; c++) mean += st[c];
    mean *= 0.1f;
    float var = 0;
    #pragma unroll
    for (int c = 0; c < 10; c++) { float d = st[c] - mean; var += d * d; }
    var *= 0.1f;
    float rstd = rsqrtf(var + 1e-5f);

    float* si = g_statsin + (size_t)r * 21;
    #pragma unroll
    for (int c = 0; c < 10; c++) si[c] = (st[c] - mean) * rstd * ln_g[c] + ln_b[c];
    si[10] = p0; si[11] = p1; si[12] = p2;
    #pragma unroll
    for (int o = 0; o < 8; o++)
        si[13 + o] = sslp_w[o*3+0] * s0 + sslp_w[o*3+1] * s1 + sslp_w[o*3+2] * s2 + sslp_b[o];
}

// ---------------- content_in assembly (fp32) ----------------
__global__ void content_assemble_kernel(const float* __restrict__ H) {
    int r = blockIdx.x;
    int b = r >> 11;
    int tid = threadIdx.x;

    int   i0 = g_ti[r*3+0], i1 = g_ti[r*3+1], i2 = g_ti[r*3+2];
    float w0 = g_twk[r*3+0], w1 = g_twk[r*3+1], w2 = g_twk[r*3+2];
    const float* Hb = H + (size_t)b * LL * DD;
    const float* Hr = H + (size_t)r * DD;
    const float* cm = g_ctx + (size_t)r * DD;
    float* dst = g_content + (size_t)r * CK;

    for (int d = tid; d < DD; d += 128) {
        dst[d] = Hr[d];
        dst[512 + d] = cm[d];
        float ct = 0.0f;
        if (i0 >= 0) ct += w0 * Hb[(size_t)i0 * DD + d];
        if (i1 >= 0) ct += w1 * Hb[(size_t)i1 * DD + d];
        if (i2 >= 0) ct += w2 * Hb[(size_t)i2 * DD + d];
        dst[1024 + d] = ct;
    }
    if (tid < 16) dst[1536 + tid] = g_curv[(size_t)r * 16 + tid];
}

// ---------------- fused stats MLP: 21 -> 64 (gelu) -> 32 ----------------
__global__ __launch_bounds__(256) void stats_mlp_kernel(
    const float* __restrict__ W1, const float* __restrict__ B1,
    const float* __restrict__ W2, const float* __restrict__ B2)
{
    __shared__ float sw1[64*22], sb1[64], sw2[32*66], sb2[32];
    __shared__ float sin_[32*22];
    __shared__ float sh[32*66];
    int r0 = blockIdx.x * 32;
    int tid = threadIdx.x;

    for (int q = tid; q < 64*21; q += 256) { int n = q/21, k = q%21; sw1[n*22+k] = W1[q]; }
    for (int q = tid; q < 32*64; q += 256) { int n = q/64, k = q%64; sw2[n*66+k] = W2[q]; }
    if (tid < 64) sb1[tid] = B1[tid];
    if (tid < 32) sb2[tid] = B2[tid];
    for (int q = tid; q < 32*21; q += 256) {
        int rr = q/21, k = q%21;
        sin_[rr*22+k] = g_statsin[(size_t)(r0+rr)*21 + k];
    }
    __syncthreads();

    int row = tid >> 3;
    #pragma unroll
    for (int j = 0; j < 8; j++) {
        int col = (tid & 7) + 8*j;
        float acc = sb1[col];
        #pragma unroll
        for (int k = 0; k < 21; k++) acc = fmaf(sin_[row*22+k], sw1[col*22+k], acc);
        sh[row*66+col] = gelu_exact(acc);
    }
    __syncthreads();
    #pragma unroll
    for (int j = 0; j < 4; j++) {
        int col = (tid & 7) + 8*j;
        float acc = sb2[col];
        #pragma unroll
        for (int k = 0; k < 64; k++) acc = fmaf(sh[row*66+k], sw2[col*66+k], acc);
        g_mrg[(size_t)(r0+row)*96 + 64 + col] = acc;
    }
}

// ---------------- fused merge MLP: 96 -> 128 (gelu) -> 64, masked ----------------
__global__ __launch_bounds__(256) void merge_mlp_kernel(
    const float* __restrict__ W1, const float* __restrict__ B1,
    const float* __restrict__ W2, const float* __restrict__ B2,
    float* __restrict__ out)
{
    extern __shared__ float dy[];
    float* sw1 = dy;
    float* sb1 = sw1 + 128*97;
    float* sw2 = sb1 + 128;
    float* sb2 = sw2 + 64*130;
    float* sin_ = sb2 + 64;
    float* sh  = sin_ + 32*97;

    int r0 = blockIdx.x * 32;
    int tid = threadIdx.x;

    for (int q = tid; q < 128*96; q += 256) { int n = q/96, k = q%96; sw1[n*97+k] = W1[q]; }
    for (int q = tid; q < 64*128; q += 256) { int n = q/128, k = q%128; sw2[n*130+k] = W2[q]; }
    if (tid < 128) sb1[tid] = B1[tid];
    if (tid < 64)  sb2[tid] = B2[tid];
    for (int q = tid; q < 32*96; q += 256) {
        int rr = q/96, k = q%96;
        sin_[rr*97+k] = g_mrg[(size_t)(r0+rr)*96 + k];
    }
    __syncthreads();

    int row = tid >> 3;
    #pragma unroll
    for (int j = 0; j < 16; j++) {
        int col = (tid & 7) + 8*j;
        float acc = sb1[col];
        #pragma unroll 8
        for (int k = 0; k < 96; k++) acc = fmaf(sin_[row*97+k], sw1[col*97+k], acc);
        sh[row*130+col] = gelu_exact(acc);
    }
    __syncthreads();
    float mf = g_mask[r0 + row] ? 1.0f : 0.0f;
    #pragma unroll
    for (int j = 0; j < 8; j++) {
        int col = (tid & 7) + 8*j;
        float acc = sb2[col];
        #pragma unroll 8
        for (int k = 0; k < 128; k++) acc = fmaf(sh[row*130+k], sw2[col*130+k], acc);
        out[(size_t)(r0+row)*64 + col] = acc * mf;
    }
}

// ---------------- host launch ----------------
extern "C" void kernel_launch(void* const* d_in, const int* in_sizes, int n_in,
                              void* d_out, int out_size) {
    const float* H      = (const float*)d_in[0];
    const float* PL     = (const float*)d_in[1];
    const float* SS     = (const float*)d_in[2];
    const float* KAPPA  = (const float*)d_in[3];
    const void*  MASK   = (const void*)d_in[4];
    const float* curv_w1 = (const float*)d_in[5];
    const float* curv_b1 = (const float*)d_in[6];
    const float* curv_w2 = (const float*)d_in[7];
    const float* curv_b2 = (const float*)d_in[8];
    const float* sslp_w  = (const float*)d_in[9];
    const float* sslp_b  = (const float*)d_in[10];
    const float* ln_g    = (const float*)d_in[11];
    const float* ln_b    = (const float*)d_in[12];
    const float* cont_w1 = (const float*)d_in[13];
    const float* cont_b1 = (const float*)d_in[14];
    const float* cont_w2 = (const float*)d_in[15];
    const float* cont_b2 = (const float*)d_in[16];
    const float* stats_w1 = (const float*)d_in[17];
    const float* stats_b1 = (const float*)d_in[18];
    const float* stats_w2 = (const float*)d_in[19];
    const float* stats_b2 = (const float*)d_in[20];
    const float* merge_w1 = (const float*)d_in[21];
    const float* merge_b1 = (const float*)d_in[22];
    const float* merge_w2 = (const float*)d_in[23];
    const float* merge_b2 = (const float*)d_in[24];
    float* out = (float*)d_out;

    __nv_bfloat16 *d_kw1hi, *d_cw1hi, *d_cw1lo;
    float *d_kb1p, *d_curv_h1, *d_curv, *d_cont_h1, *d_content, *d_mrg;
    cudaGetSymbolAddress((void**)&d_cw1hi, g_cw1hi);
    cudaGetSymbolAddress((void**)&d_cw1lo, g_cw1lo);
    cudaGetSymbolAddress((void**)&d_kw1hi, g_kw1hi);
    cudaGetSymbolAddress((void**)&d_kb1p, g_kb1p);
    cudaGetSymbolAddress((void**)&d_curv_h1, g_curv_h1);
    cudaGetSymbolAddress((void**)&d_curv, g_curv);
    cudaGetSymbolAddress((void**)&d_cont_h1, g_cont_h1);
    cudaGetSymbolAddress((void**)&d_content, g_content);
    cudaGetSymbolAddress((void**)&d_mrg, g_mrg);

    static cudaStream_t s1, s2;
    static cudaEvent_t ev_conv, ev_rsb[BB], ev_ctx, ev_curv, ev_stats;
    static int init_done = 0;
    if (!init_done) {
        cudaFuncSetAttribute(merge_mlp_kernel,
                             cudaFuncAttributeMaxDynamicSharedMemorySize, 113000);
        cudaFuncSetAttribute(ctx_gemm_kernel,
                             cudaFuncAttributeMaxDynamicSharedMemorySize, CTX_SMEM_BYTES);
        cudaStreamCreateWithFlags(&s1, cudaStreamNonBlocking);
        cudaStreamCreateWithFlags(&s2, cudaStreamNonBlocking);
        cudaEventCreateWithFlags(&ev_conv,  cudaEventDisableTiming);
        for (int b = 0; b < BB; b++)
            cudaEventCreateWithFlags(&ev_rsb[b], cudaEventDisableTiming);
        cudaEventCreateWithFlags(&ev_ctx,   cudaEventDisableTiming);
        cudaEventCreateWithFlags(&ev_curv,  cudaEventDisableTiming);
        cudaEventCreateWithFlags(&ev_stats, cudaEventDisableTiming);
        init_done = 1;
    }

    int write_stats = (out_size >= BL * 64 + BL * 10) ? 1 : 0;
    int merge_smem = (128*97 + 128 + 64*130 + 64 + 32*97 + 32*130) * 4;

    // ---- main stream (default) ----
    convert_all_kernel<<<2048, 256>>>(H, cont_w1, curv_w1, curv_b1);
    cudaEventRecord(ev_conv, 0);
    mask_expand_kernel<<<BL/256, 256>>>(MASK);

    // batch-pipelined row_stats (main) / ctx (s2)
    for (int b = 0; b < BB; b++) {
        row_stats_kernel<<<LL, 256>>>(PL, b * LL);
        cudaEventRecord(ev_rsb[b], 0);
        cudaStreamWaitEvent(s2, ev_rsb[b], 0);
        ctx_gemm_kernel<<<dim3(LL/128, DD/128), 256, CTX_SMEM_BYTES, s2>>>(b);
    }
    cudaEventRecord(ev_ctx, s2);

    // ---- side stream s1: curv chain, then stats chain ----
    cudaStreamWaitEvent(s1, ev_conv, 0);
    wmma_hilo_gemm_f32A<1,0><<<dim3(BL/128, 4), 256, 0, s1>>>(KAPPA, d_kw1hi, nullptr,
                                                              d_kb1p, d_curv_h1, 496, 248, 248);
    simt_gemm<0><<<dim3(BL/64, 1), 256, 0, s1>>>(d_curv_h1, curv_w2, curv_b2, d_curv, BL, 16, 248, 16);
    cudaEventRecord(ev_curv, s1);
    cudaStreamWaitEvent(s1, ev_rsb[BB-1], 0);
    stats_finalize_kernel<<<BL/256, 256, 0, s1>>>(SS, sslp_w, sslp_b, ln_g, ln_b, out, write_stats);
    stats_mlp_kernel<<<BL/32, 256, 0, s1>>>(stats_w1, stats_b1, stats_w2, stats_b2);
    cudaEventRecord(ev_stats, s1);

    // ---- main stream continues after ctx + curv ----
    cudaStreamWaitEvent(0, ev_ctx, 0);
    cudaStreamWaitEvent(0, ev_curv, 0);
    content_assemble_kernel<<<BL, 128>>>(H);
    wmma_hilo_gemm_f32A<1,1><<<dim3(BL/128, 2), 256>>>(d_content, d_cw1hi, d_cw1lo,
                                                       cont_b1, d_cont_h1, CK, 128, 128);
    simt_gemm<0><<<dim3(BL/64, 1), 256>>>(d_cont_h1, cont_w2, cont_b2, d_mrg, BL, 64, 128, 96);
    cudaStreamWaitEvent(0, ev_stats, 0);
    merge_mlp_kernel<<<BL/32, 256, merge_smem>>>(merge_w1, merge_b1, merge_w2, merge_b2, out);
}

// round 15
// speedup vs baseline: 1.3411x; 1.3411x over previous
#include <cuda_runtime.h>
#include <cuda_bf16.h>
#include <mma.h>
#include <math.h>

using namespace nvcuda;

#define BB 4
#define LL 2048
#define DD 512
#define BL (BB*LL)

#define NEGV     (-10000.0f)
#define INV_TAU  (1.0f/1.5f)
#define INV_TAU_SS 0.8f
#define LOG2E    1.4426950408889634f
#define LN2      0.6931471805599453f

#define CK 1552   // content K

// ---------------- scratch (static device memory) ----------------
__device__ __nv_bfloat16 g_attn[(size_t)BL * LL];     // 33.5 MB
__device__ __nv_bfloat16 g_Hbf[(size_t)BL * DD];
__device__ float g_ctx[(size_t)BL * DD];
__device__ float g_content[(size_t)BL * CK];
__device__ __nv_bfloat16 g_cw1hi[128*CK], g_cw1lo[128*CK];
__device__ __nv_bfloat16 g_kw1hi[256*496];            // padded N 248->256 (2-term)
__device__ float g_kb1p[256];
__device__ float g_curv_h1[(size_t)BL * 248];
__device__ float g_curv[(size_t)BL * 16];
__device__ float g_cont_h1[(size_t)BL * 128];
__device__ float g_statsin[(size_t)BL * 21];
__device__ float g_mrg[(size_t)BL * 96];
__device__ float g_pm[BL], g_mpp[BL], g_unp[BL], g_pen[BL], g_lm[BL], g_dm[BL];
__device__ int   g_ti[BL*3];
__device__ float g_twk[BL*3];
__device__ int   g_nb[BB];
__device__ unsigned char g_mask[BL];

// ---------------- helpers ----------------
__device__ inline float nan_fix(float x) {
    if (isnan(x)) return 0.0f;
    if (isinf(x)) return x > 0.0f ? 1.0f : 0.0f;
    return x;
}

__device__ inline float gelu_exact(float x) {
    return 0.5f * x * (1.0f + erff(x * 0.70710678118654752f));
}

__device__ inline unsigned ord_pack(float x) {
    unsigned u = __float_as_uint(x);
    return u ^ ((unsigned)(((int)u) >> 31) | 0x80000000u);
}
__device__ inline float ord_unpack(unsigned m) {
    unsigned u = (m & 0x80000000u) ? (m ^ 0x80000000u) : ~m;
    return __uint_as_float(u);
}

__device__ inline void cp_async16(void* smem_dst, const void* gmem_src) {
    unsigned sa = (unsigned)__cvta_generic_to_shared(smem_dst);
    asm volatile("cp.async.cg.shared.global [%0], [%1], 16;\n" :: "r"(sa), "l"(gmem_src));
}

// ---------------- H -> bf16 + all weight conversions (also zeroes g_nb) ----------------
__global__ void convert_all_kernel(const float* __restrict__ H,
                                   const float* __restrict__ cw1,
                                   const float* __restrict__ kw1,
                                   const float* __restrict__ kb1) {
    int idx = blockIdx.x * blockDim.x + threadIdx.x;
    if (blockIdx.x == 0 && threadIdx.x < BB) g_nb[threadIdx.x] = 0;

    int nH = BL * DD / 4;
    int n1 = 128 * CK;
    int n2 = 256 * 496;
    int ntot = nH + n1 + n2 + 256;

    for (; idx < ntot; idx += gridDim.x * blockDim.x) {
        if (idx < nH) {
            float4 v = ((const float4*)H)[idx];
            __nv_bfloat162 a = __floats2bfloat162_rn(v.x, v.y);
            __nv_bfloat162 b = __floats2bfloat162_rn(v.z, v.w);
            ((__nv_bfloat162*)g_Hbf)[idx*2]   = a;
            ((__nv_bfloat162*)g_Hbf)[idx*2+1] = b;
        } else if (idx < nH + n1) {
            int q = idx - nH;
            float x = cw1[q];
            __nv_bfloat16 h = __float2bfloat16(x);
            g_cw1hi[q] = h;
            g_cw1lo[q] = __float2bfloat16(x - __bfloat162float(h));
        } else if (idx < nH + n1 + n2) {
            int q = idx - nH - n1;
            float x = (q < 248*496) ? kw1[q] : 0.0f;
            g_kw1hi[q] = __float2bfloat16(x);
        } else {
            int q = idx - nH - n1 - n2;
            g_kb1p[q] = (q < 248) ? kb1[q] : 0.0f;
        }
    }
}

// ---------------- mask expand (dtype detect inline) ----------------
__global__ void mask_expand_kernel(const void* M) {
    int idx = blockIdx.x * blockDim.x + threadIdx.x;
    if (idx >= BL) return;
    unsigned int w = *(const unsigned int*)M;
    int mode;
    if      (w == 0x01010101u) mode = 0;
    else if (w == 0x3F800000u) mode = 2;
    else if (w == 0x3F803F80u) mode = 3;
    else                       mode = 1;
    unsigned char v;
    if      (mode == 0) v = ((const unsigned char*)M)[idx] != 0;
    else if (mode == 1) v = ((const int*)M)[idx] != 0;
    else if (mode == 2) v = ((const float*)M)[idx] != 0.0f;
    else                v = ((const unsigned short*)M)[idx] != 0;
    g_mask[idx] = v;
    unsigned int ball = __ballot_sync(0xffffffffu, v != 0);
    if ((idx & 31) == 0) atomicAdd(&g_nb[idx >> 11], __popc(ball));
}

// ---------------- fused row stats v3 (REDUX top-3) ----------------
__global__ __launch_bounds__(256) void row_stats_kernel(const float* __restrict__ PL)
{
    __shared__ unsigned swm[8];
    __shared__ unsigned swi[8];
    __shared__ float redf[8*3];
    __shared__ float bc[4];

    int r = blockIdx.x;
    int b = r >> 11;
    int i = r & (LL - 1);
    int tid = threadIdx.x;
    int lane = tid & 31, wid = tid >> 5;

    const float* row = PL + (size_t)r * LL;
    const unsigned char* mrow = g_mask + (size_t)b * LL;
    int Nb = g_nb[b];
    bool allv = (Nb == LL);
    bool mi = mrow[i] != 0;

    int j0 = tid * 8;
    float x[8];
    *(float4*)&x[0] = *(const float4*)&row[j0];
    *(float4*)&x[4] = *(const float4*)&row[j0 + 4];

    if (mi && allv) {
        if (i >= j0 && i < j0 + 8) x[i - j0] = NEGV;
    } else if (!mi) {
        #pragma unroll
        for (int t = 0; t < 8; t++) x[t] = NEGV;
    } else {
        #pragma unroll
        for (int t = 0; t < 8; t++) {
            int j = j0 + t;
            if (j == i || !mrow[j]) x[t] = NEGV;
        }
    }

    unsigned ou[8];
    #pragma unroll
    for (int t = 0; t < 8; t++) ou[t] = ord_pack(x[t]);

    unsigned selv[3], seli[3];
    #pragma unroll
    for (int k3 = 0; k3 < 3; k3++) {
        unsigned tm = ou[0];
        #pragma unroll
        for (int t = 1; t < 8; t++) tm = max(tm, ou[t]);
        unsigned wm = __reduce_max_sync(0xffffffffu, tm);
        if (lane == 0) swm[wid] = wm;
        __syncthreads();
        unsigned M = swm[0];
        #pragma unroll
        for (int w = 1; w < 8; w++) M = max(M, swm[w]);

        unsigned mi_idx = 0xFFFFFFFFu;
        #pragma unroll
        for (int t = 0; t < 8; t++)
            if (ou[t] == M) mi_idx = min(mi_idx, (unsigned)(j0 + t));
        unsigned wmi = __reduce_min_sync(0xffffffffu, mi_idx);
        if (lane == 0) swi[wid] = wmi;
        __syncthreads();
        unsigned I = swi[0];
        #pragma unroll
        for (int w = 1; w < 8; w++) I = min(I, swi[w]);

        selv[k3] = M; seli[k3] = I;
        if (I >= (unsigned)j0 && I < (unsigned)(j0 + 8)) ou[I - j0] = 0u;
    }

    float m = ord_unpack(selv[0]);
    float mx2 = m * (INV_TAU * LOG2E);
    float enm = exp2f(-mx2);

    float S = 0.0f, T2 = 0.0f, G = 0.0f;
    #pragma unroll
    for (int t = 0; t < 8; t++) {
        float d2 = fmaf(x[t], INV_TAU * LOG2E, -mx2);
        float e = exp2f(d2);
        S += e;
        T2 = fmaf(e, d2, T2);
        float sg = __fdividef(e, e + enm);
        G += sg;
    }
    #pragma unroll
    for (int off = 16; off >= 1; off >>= 1) {
        S  += __shfl_down_sync(0xffffffffu, S, off);
        T2 += __shfl_down_sync(0xffffffffu, T2, off);
        G  += __shfl_down_sync(0xffffffffu, G, off);
    }
    if (lane == 0) { redf[wid*3+0] = S; redf[wid*3+1] = T2; redf[wid*3+2] = G; }
    __syncthreads();
    if (wid == 0) {
        float s = 0, t2 = 0, g = 0;
        if (lane < 8) { s = redf[lane*3+0]; t2 = redf[lane*3+1]; g = redf[lane*3+2]; }
        #pragma unroll
        for (int off = 4; off >= 1; off >>= 1) {
            s  += __shfl_down_sync(0xffffffffu, s, off);
            t2 += __shfl_down_sync(0xffffffffu, t2, off);
            g  += __shfl_down_sync(0xffffffffu, g, off);
        }
        int jw = i - 8 + lane;
        float gl = 0.0f;
        if (lane < 17 && jw >= 0 && jw < LL) {
            float xw = row[jw];
            bool valid = mi && (jw != i) && (allv || mrow[jw]);
            if (!valid) xw = NEGV;
            float d2 = fmaf(xw, INV_TAU * LOG2E, -mx2);
            float e = exp2f(d2);
            gl = __fdividef(e, e + enm);
        }
        #pragma unroll
        for (int off = 16; off >= 1; off >>= 1)
            gl += __shfl_down_sync(0xffffffffu, gl, off);
        if (lane == 0) { bc[0] = s; bc[1] = t2; bc[2] = g; bc[3] = gl; }
    }
    __syncthreads();

    float St = bc[0];
    float invS = __fdividef(1.0f, St);

    __nv_bfloat162 ob[4];
    #pragma unroll
    for (int p = 0; p < 4; p++) {
        float e0 = exp2f(fmaf(x[2*p],   INV_TAU * LOG2E, -mx2));
        float e1 = exp2f(fmaf(x[2*p+1], INV_TAU * LOG2E, -mx2));
        ob[p] = __floats2bfloat162_rn(e0 * invS, e1 * invS);
    }
    *(uint4*)&g_attn[(size_t)r * LL + j0] = *(uint4*)ob;

    if (tid == 0) {
        float Tt = bc[1] * LN2;
        float Gt = bc[2];
        float Glt = bc[3];

        int lo = i - 8 < 0 ? 0 : i - 8;
        int hi = i + 8 > LL-1 ? LL-1 : i + 8;
        float wcount;
        if (allv) wcount = (float)(hi - lo + 1);
        else { int c = 0; for (int j = lo; j <= hi; j++) c += mrow[j]; wcount = (float)c; }
        float nvalid  = mi ? (float)(Nb - 1) : 0.0f;
        float nlocal  = mi ? (wcount - 1.0f) : 0.0f;
        float ndistal = nvalid - nlocal;

        float entropy = logf(St) - Tt / St;
        float maxpp = __fdividef(1.0f, 1.0f + enm);
        float pen = entropy / fmaxf(logf(fmaxf(nvalid, 1.0f)), 1e-4f);
        pen = fminf(fmaxf(pen, 0.0f), 1.0f);

        g_pm[r]  = __fdividef(Gt, fmaxf(nvalid, 1.0f));
        g_mpp[r] = maxpp;
        g_unp[r] = 1.0f - maxpp;
        g_pen[r] = nan_fix(pen);
        g_lm[r]  = __fdividef(Glt, fmaxf(nlocal, 1.0f));
        g_dm[r]  = __fdividef(Gt - Glt, fmaxf(ndistal, 1.0f));

        float tvv[3] = {ord_unpack(selv[0]), ord_unpack(selv[1]), ord_unpack(selv[2])};
        float mt = (tvv[0] > -9000.0f) ? tvv[0] : NEGV;
        float a[3]; float ssum = 0.0f;
        #pragma unroll
        for (int k = 0; k < 3; k++) {
            bool val = tvv[k] > -9000.0f;
            a[k] = val ? __expf((tvv[k] - mt) * INV_TAU) : 0.0f;
            ssum += a[k];
        }
        float inv = __fdividef(1.0f, fmaxf(ssum, 1e-8f));
        #pragma unroll
        for (int k = 0; k < 3; k++) {
            g_twk[r*3+k] = a[k] * inv;
            g_ti[r*3+k]  = (int)seli[k];
        }
    }
}

// ---------------- ctx = attn @ H (wmma, 3-stage, R9 scheme), full grid ----------------
#define CTX_STAGE_A (128*40)
#define CTX_STAGE_B (32*136)
#define CTX_STAGE_ELEMS (CTX_STAGE_A + CTX_STAGE_B)
#define CTX_SMEM_BYTES (3 * CTX_STAGE_ELEMS * 2)

__global__ __launch_bounds__(256, 2) void ctx_gemm_kernel() {
    extern __shared__ __align__(16) __nv_bfloat16 smem_ctx[];
    __nv_bfloat16* As[3];
    __nv_bfloat16* Bs[3];
    #pragma unroll
    for (int s = 0; s < 3; s++) {
        As[s] = smem_ctx + s * CTX_STAGE_ELEMS;
        Bs[s] = As[s] + CTX_STAGE_A;
    }

    int m0 = blockIdx.x * 128;
    int n0 = blockIdx.y * 128;
    int b  = blockIdx.z;
    const __nv_bfloat16* A  = g_attn + (size_t)b * LL * LL;
    const __nv_bfloat16* Bm = g_Hbf  + (size_t)b * LL * DD;
    float* C = g_ctx + (size_t)b * LL * DD;

    int tid = threadIdx.x;
    int wid = tid >> 5;
    int wm = wid & 3;
    int wn = wid >> 2;

    wmma::fragment<wmma::accumulator, 16, 16, 16, float> acc[2][4];
    #pragma unroll
    for (int x = 0; x < 2; x++)
        #pragma unroll
        for (int y = 0; y < 4; y++)
            wmma::fill_fragment(acc[x][y], 0.0f);

    auto load_stage = [&](int st, int k0) {
        #pragma unroll
        for (int it = 0; it < 2; it++) {
            int q = tid + it * 256;
            int rowA = q >> 2, c4 = q & 3;
            cp_async16(&As[st][rowA * 40 + c4 * 8],
                       &A[(size_t)(m0 + rowA) * LL + k0 + c4 * 8]);
            int rowB = q >> 4, c16 = q & 15;
            cp_async16(&Bs[st][rowB * 136 + c16 * 8],
                       &Bm[(size_t)(k0 + rowB) * DD + n0 + c16 * 8]);
        }
        asm volatile("cp.async.commit_group;\n" ::: "memory");
    };

    load_stage(0, 0);
    load_stage(1, 32);
    load_stage(2, 64);

    for (int c = 0; c < 64; c++) {
        int st = c % 3;
        if (c < 62) asm volatile("cp.async.wait_group 2;\n" ::: "memory");
        else        asm volatile("cp.async.wait_group 0;\n" ::: "memory");
        __syncthreads();
        #pragma unroll
        for (int kk = 0; kk < 32; kk += 16) {
            wmma::fragment<wmma::matrix_a, 16, 16, 16, __nv_bfloat16, wmma::row_major> af[2];
            wmma::fragment<wmma::matrix_b, 16, 16, 16, __nv_bfloat16, wmma::row_major> bf[4];
            #pragma unroll
            for (int x = 0; x < 2; x++)
                wmma::load_matrix_sync(af[x], &As[st][(wm*32 + x*16) * 40 + kk], 40);
            #pragma unroll
            for (int y = 0; y < 4; y++)
                wmma::load_matrix_sync(bf[y], &Bs[st][kk * 136 + wn*64 + y*16], 136);
            #pragma unroll
            for (int x = 0; x < 2; x++)
                #pragma unroll
                for (int y = 0; y < 4; y++)
                    wmma::mma_sync(acc[x][y], af[x], bf[y], acc[x][y]);
        }
        __syncthreads();
        if (c + 3 < 64) load_stage(st, (c + 3) * 32);
    }

    #pragma unroll
    for (int x = 0; x < 2; x++)
        #pragma unroll
        for (int y = 0; y < 4; y++)
            wmma::store_matrix_sync(
                C + (size_t)(m0 + wm*32 + x*16) * DD + n0 + wn*64 + y*16,
                acc[x][y], DD, wmma::mem_row_major);
}

// ---------------- hi/lo bf16 tensor-core GEMM, fp32 A split in-kernel ----------------
template<int ACT, int PREC>
__global__ __launch_bounds__(256) void wmma_hilo_gemm_f32A(
    const float* __restrict__ A,
    const __nv_bfloat16* __restrict__ Whi, const __nv_bfloat16* __restrict__ Wlo,
    const float* __restrict__ bias, float* __restrict__ C,
    int K, int Nout, int ldc)
{
    __shared__ __align__(16) char sraw[35840];
    __nv_bfloat16* sAhi = (__nv_bfloat16*)sraw;
    __nv_bfloat16* sAlo = sAhi + 128*40;
    __nv_bfloat16* sWhi = sAlo + 128*40;
    __nv_bfloat16* sWlo = sWhi + 64*40;
    float* stage = (float*)sraw;

    int m0 = blockIdx.x * 128;
    int n0 = blockIdx.y * 64;
    int tid = threadIdx.x, wid = tid >> 5;
    int wm = wid & 3, wn = wid >> 2;

    wmma::fragment<wmma::accumulator, 16, 16, 16, float> acc[2][2];
    #pragma unroll
    for (int x = 0; x < 2; x++)
        #pragma unroll
        for (int y = 0; y < 2; y++)
            wmma::fill_fragment(acc[x][y], 0.0f);

    int Kpad = (K + 31) & ~31;
    for (int k0 = 0; k0 < Kpad; k0 += 32) {
        #pragma unroll
        for (int it = 0; it < 4; it++) {
            int q = tid + it * 256;
            int rowA = q >> 3, c = q & 7;
            int kidx = k0 + c * 4;
            float4 v = make_float4(0.f, 0.f, 0.f, 0.f);
            if (kidx < K)
                v = *(const float4*)&A[(size_t)(m0 + rowA) * K + kidx];
            float xs[4] = {v.x, v.y, v.z, v.w};
            #pragma unroll
            for (int u = 0; u < 4; u++) {
                __nv_bfloat16 h = __float2bfloat16(xs[u]);
                sAhi[rowA*40 + c*4 + u] = h;
                sAlo[rowA*40 + c*4 + u] = __float2bfloat16(xs[u] - __bfloat162float(h));
            }
        }
        {
            int rowN = tid >> 2, c4 = tid & 3;
            int kidx = k0 + c4 * 8;
            uint4 vh = make_uint4(0,0,0,0), vl = make_uint4(0,0,0,0);
            if (kidx < K) {
                vh = *(const uint4*)&Whi[(size_t)(n0 + rowN) * K + kidx];
                if (PREC) vl = *(const uint4*)&Wlo[(size_t)(n0 + rowN) * K + kidx];
            }
            *(uint4*)&sWhi[rowN * 40 + c4 * 8] = vh;
            if (PREC) *(uint4*)&sWlo[rowN * 40 + c4 * 8] = vl;
        }
        __syncthreads();
        #pragma unroll
        for (int kk = 0; kk < 32; kk += 16) {
            wmma::fragment<wmma::matrix_a, 16, 16, 16, __nv_bfloat16, wmma::row_major> ah[2], al[2];
            wmma::fragment<wmma::matrix_b, 16, 16, 16, __nv_bfloat16, wmma::col_major> bh[2], bl[2];
            #pragma unroll
            for (int x = 0; x < 2; x++) {
                wmma::load_matrix_sync(ah[x], &sAhi[(wm*32 + x*16) * 40 + kk], 40);
                wmma::load_matrix_sync(al[x], &sAlo[(wm*32 + x*16) * 40 + kk], 40);
            }
            #pragma unroll
            for (int y = 0; y < 2; y++) {
                wmma::load_matrix_sync(bh[y], &sWhi[(wn*32 + y*16) * 40 + kk], 40);
                if (PREC) wmma::load_matrix_sync(bl[y], &sWlo[(wn*32 + y*16) * 40 + kk], 40);
            }
            #pragma unroll
            for (int x = 0; x < 2; x++)
                #pragma unroll
                for (int y = 0; y < 2; y++) {
                    wmma::mma_sync(acc[x][y], ah[x], bh[y], acc[x][y]);
                    if (PREC) wmma::mma_sync(acc[x][y], ah[x], bl[y], acc[x][y]);
                    wmma::mma_sync(acc[x][y], al[x], bh[y], acc[x][y]);
                }
        }
        __syncthreads();
    }

    #pragma unroll
    for (int x = 0; x < 2; x++)
        #pragma unroll
        for (int y = 0; y < 2; y++)
            wmma::store_matrix_sync(&stage[(wm*32 + x*16) * 68 + wn*32 + y*16],
                                    acc[x][y], 68, wmma::mem_row_major);
    __syncthreads();
    #pragma unroll
    for (int t = 0; t < 32; t++) {
        int q = tid + t * 256;
        int rowm = q >> 6, col = q & 63;
        int n = n0 + col;
        if (n < Nout) {
            float c = stage[rowm * 68 + col] + bias[n];
            if (ACT == 1) c = gelu_exact(c);
            C[(size_t)(m0 + rowm) * ldc + n] = c;
        }
    }
}

// ---------------- SIMT fp32 GEMM (small layers) ----------------
template<int ACT>
__global__ __launch_bounds__(256) void simt_gemm(
    const float* __restrict__ A, const float* __restrict__ W,
    const float* __restrict__ bias, float* __restrict__ C,
    int M, int N, int K, int ldc)
{
    __shared__ __align__(16) float As[16][68];
    __shared__ __align__(16) float Ws[16][68];
    int m0 = blockIdx.x * 64;
    int n0 = blockIdx.y * 64;
    int tid = threadIdx.x;
    int tr = tid & 15, tc = tid >> 4;

    float acc[4][4] = {};

    for (int k0 = 0; k0 < K; k0 += 16) {
        #pragma unroll
        for (int it = 0; it < 4; it++) {
            int q = tid + it * 256;
            int m = q >> 4, k = q & 15;
            As[k][m] = (k0 + k < K) ? A[(size_t)(m0 + m) * K + k0 + k] : 0.0f;
            int n = m;
            Ws[k][n] = (n0 + n < N && k0 + k < K) ? W[(size_t)(n0 + n) * K + k0 + k] : 0.0f;
        }
        __syncthreads();
        #pragma unroll
        for (int kk = 0; kk < 16; kk++) {
            float4 av = *(const float4*)&As[kk][tr * 4];
            float4 wv = *(const float4*)&Ws[kk][tc * 4];
            float a4[4] = {av.x, av.y, av.z, av.w};
            float w4[4] = {wv.x, wv.y, wv.z, wv.w};
            #pragma unroll
            for (int x = 0; x < 4; x++)
                #pragma unroll
                for (int y = 0; y < 4; y++)
                    acc[x][y] += a4[x] * w4[y];
        }
        __syncthreads();
    }

    #pragma unroll
    for (int x = 0; x < 4; x++) {
        int m = m0 + tr * 4 + x;
        #pragma unroll
        for (int y = 0; y < 4; y++) {
            int n = n0 + tc * 4 + y;
            if (n < N) {
                float c = acc[x][y] + bias[n];
                if (ACT == 1) c = gelu_exact(c);
                C[(size_t)m * ldc + n] = c;
            }
        }
    }
}

// ---------------- stats finalize + layernorm + ss ----------------
__global__ void stats_finalize_kernel(
    const float* __restrict__ SS,
    const float* __restrict__ sslp_w, const float* __restrict__ sslp_b,
    const float* __restrict__ ln_g, const float* __restrict__ ln_b,
    float* __restrict__ out, int write_stats)
{
    int r = blockIdx.x * blockDim.x + threadIdx.x;
    if (r >= BL) return;
    int b = r >> 11;
    int i = r & (LL - 1);
    const unsigned char* mrow = g_mask + (size_t)b * LL;
    float mf = mrow[i] ? 1.0f : 0.0f;

    const float* s = SS + (size_t)r * 3;
    float s0 = s[0], s1 = s[1], s2 = s[2];
    float t0 = s0 * INV_TAU_SS, t1 = s1 * INV_TAU_SS, t2 = s2 * INV_TAU_SS;
    float mss = fmaxf(t0, fmaxf(t1, t2));
    float e0 = __expf(t0 - mss), e1 = __expf(t1 - mss), e2 = __expf(t2 - mss);
    float es = e0 + e1 + e2;
    float p0 = e0 / es, p1 = e1 / es, p2 = e2 / es;
    float ssent = -(p0 * logf(p0 + 1e-8f) + p1 * logf(p1 + 1e-8f) + p2 * logf(p2 + 1e-8f));

    float sx3 = 0, sm3 = 0, sx7 = 0, sm7 = 0, se7 = 0;
    for (int d = -5; d <= 5; d++) {
        int j = i + d;
        if (j < 0 || j >= LL) continue;
        float mfj = mrow[j] ? 1.0f : 0.0f;
        int rj = b * LL + j;
        float u = g_unp[rj] * mfj;
        float p = g_pen[rj] * mfj;
        if (d >= -2 && d <= 2) { sx3 += u; sm3 += mfj; }
        sx7 += u; sm7 += mfj; se7 += p;
    }
    float w3 = sx3 / fmaxf(sm3, 1.0f);
    float w7 = sx7 / fmaxf(sm7, 1.0f);
    float e7 = se7 / fmaxf(sm7, 1.0f);

    float st[10];
    st[0] = g_pm[r]; st[1] = g_mpp[r]; st[2] = g_unp[r]; st[3] = g_pen[r];
    st[4] = ssent;   st[5] = g_lm[r];  st[6] = g_dm[r];
    st[7] = w3; st[8] = w7; st[9] = e7;
    #pragma unroll
    for (int c = 0; c < 10; c++) st[c] = nan_fix(st[c] * mf);

    if (write_stats) {
        float* os = out + (size_t)BL * 64 + (size_t)r * 10;
        #pragma unroll
        for (int c = 0; c < 10; c++) os[c] = st[c];
    }

    float mean = 0;
    #pragma unroll
    for (int c = 0; c < 10; c++) mean += st[c];
    mean *= 0.1f;
    float var = 0;
    #pragma unroll
    for (int c = 0; c < 10; c++) { float d = st[c] - mean; var += d * d; }
    var *= 0.1f;
    float rstd = rsqrtf(var + 1e-5f);

    float* si = g_statsin + (size_t)r * 21;
    #pragma unroll
    for (int c = 0; c < 10; c++) si[c] = (st[c] - mean) * rstd * ln_g[c] + ln_b[c];
    si[10] = p0; si[11] = p1; si[12] = p2;
    #pragma unroll
    for (int o = 0; o < 8; o++)
        si[13 + o] = sslp_w[o*3+0] * s0 + sslp_w[o*3+1] * s1 + sslp_w[o*3+2] * s2 + sslp_b[o];
}

// ---------------- content assembly A: H, topk, curv (cols 0-511, 1024-1551) ----------------
__global__ void content_assembleA_kernel(const float* __restrict__ H) {
    int r = blockIdx.x;
    int b = r >> 11;
    int tid = threadIdx.x;

    int   i0 = g_ti[r*3+0], i1 = g_ti[r*3+1], i2 = g_ti[r*3+2];
    float w0 = g_twk[r*3+0], w1 = g_twk[r*3+1], w2 = g_twk[r*3+2];
    const float* Hb = H + (size_t)b * LL * DD;
    const float* Hr = H + (size_t)r * DD;
    float* dst = g_content + (size_t)r * CK;

    for (int d = tid; d < DD; d += 128) {
        dst[d] = Hr[d];
        float ct = 0.0f;
        if (i0 >= 0) ct += w0 * Hb[(size_t)i0 * DD + d];
        if (i1 >= 0) ct += w1 * Hb[(size_t)i1 * DD + d];
        if (i2 >= 0) ct += w2 * Hb[(size_t)i2 * DD + d];
        dst[1024 + d] = ct;
    }
    if (tid < 16) dst[1536 + tid] = g_curv[(size_t)r * 16 + tid];
}

// ---------------- content assembly B: ctx columns (512-1023) ----------------
__global__ void content_assembleB_kernel() {
    int r = blockIdx.x;
    int tid = threadIdx.x;
    const float4* cm = (const float4*)(g_ctx + (size_t)r * DD);
    float4* dst = (float4*)(g_content + (size_t)r * CK + 512);
    dst[tid] = cm[tid];   // 128 threads x float4 = 512 floats
}

// ---------------- fused stats MLP: 21 -> 64 (gelu) -> 32 ----------------
__global__ __launch_bounds__(256) void stats_mlp_kernel(
    const float* __restrict__ W1, const float* __restrict__ B1,
    const float* __restrict__ W2, const float* __restrict__ B2)
{
    __shared__ float sw1[64*22], sb1[64], sw2[32*66], sb2[32];
    __shared__ float sin_[32*22];
    __shared__ float sh[32*66];
    int r0 = blockIdx.x * 32;
    int tid = threadIdx.x;

    for (int q = tid; q < 64*21; q += 256) { int n = q/21, k = q%21; sw1[n*22+k] = W1[q]; }
    for (int q = tid; q < 32*64; q += 256) { int n = q/64, k = q%64; sw2[n*66+k] = W2[q]; }
    if (tid < 64) sb1[tid] = B1[tid];
    if (tid < 32) sb2[tid] = B2[tid];
    for (int q = tid; q < 32*21; q += 256) {
        int rr = q/21, k = q%21;
        sin_[rr*22+k] = g_statsin[(size_t)(r0+rr)*21 + k];
    }
    __syncthreads();

    int row = tid >> 3;
    #pragma unroll
    for (int j = 0; j < 8; j++) {
        int col = (tid & 7) + 8*j;
        float acc = sb1[col];
        #pragma unroll
        for (int k = 0; k < 21; k++) acc = fmaf(sin_[row*22+k], sw1[col*22+k], acc);
        sh[row*66+col] = gelu_exact(acc);
    }
    __syncthreads();
    #pragma unroll
    for (int j = 0; j < 4; j++) {
        int col = (tid & 7) + 8*j;
        float acc = sb2[col];
        #pragma unroll
        for (int k = 0; k < 64; k++) acc = fmaf(sh[row*66+k], sw2[col*66+k], acc);
        g_mrg[(size_t)(r0+row)*96 + 64 + col] = acc;
    }
}

// ---------------- fused merge MLP: 96 -> 128 (gelu) -> 64, masked ----------------
__global__ __launch_bounds__(256) void merge_mlp_kernel(
    const float* __restrict__ W1, const float* __restrict__ B1,
    const float* __restrict__ W2, const float* __restrict__ B2,
    float* __restrict__ out)
{
    extern __shared__ float dy[];
    float* sw1 = dy;
    float* sb1 = sw1 + 128*97;
    float* sw2 = sb1 + 128;
    float* sb2 = sw2 + 64*130;
    float* sin_ = sb2 + 64;
    float* sh  = sin_ + 32*97;

    int r0 = blockIdx.x * 32;
    int tid = threadIdx.x;

    for (int q = tid; q < 128*96; q += 256) { int n = q/96, k = q%96; sw1[n*97+k] = W1[q]; }
    for (int q = tid; q < 64*128; q += 256) { int n = q/128, k = q%128; sw2[n*130+k] = W2[q]; }
    if (tid < 128) sb1[tid] = B1[tid];
    if (tid < 64)  sb2[tid] = B2[tid];
    for (int q = tid; q < 32*96; q += 256) {
        int rr = q/96, k = q%96;
        sin_[rr*97+k] = g_mrg[(size_t)(r0+rr)*96 + k];
    }
    __syncthreads();

    int row = tid >> 3;
    #pragma unroll
    for (int j = 0; j < 16; j++) {
        int col = (tid & 7) + 8*j;
        float acc = sb1[col];
        #pragma unroll 8
        for (int k = 0; k < 96; k++) acc = fmaf(sin_[row*97+k], sw1[col*97+k], acc);
        sh[row*130+col] = gelu_exact(acc);
    }
    __syncthreads();
    float mf = g_mask[r0 + row] ? 1.0f : 0.0f;
    #pragma unroll
    for (int j = 0; j < 8; j++) {
        int col = (tid & 7) + 8*j;
        float acc = sb2[col];
        #pragma unroll 8
        for (int k = 0; k < 128; k++) acc = fmaf(sh[row*130+k], sw2[col*130+k], acc);
        out[(size_t)(r0+row)*64 + col] = acc * mf;
    }
}

// ---------------- host launch ----------------
extern "C" void kernel_launch(void* const* d_in, const int* in_sizes, int n_in,
                              void* d_out, int out_size) {
    const float* H      = (const float*)d_in[0];
    const float* PL     = (const float*)d_in[1];
    const float* SS     = (const float*)d_in[2];
    const float* KAPPA  = (const float*)d_in[3];
    const void*  MASK   = (const void*)d_in[4];
    const float* curv_w1 = (const float*)d_in[5];
    const float* curv_b1 = (const float*)d_in[6];
    const float* curv_w2 = (const float*)d_in[7];
    const float* curv_b2 = (const float*)d_in[8];
    const float* sslp_w  = (const float*)d_in[9];
    const float* sslp_b  = (const float*)d_in[10];
    const float* ln_g    = (const float*)d_in[11];
    const float* ln_b    = (const float*)d_in[12];
    const float* cont_w1 = (const float*)d_in[13];
    const float* cont_b1 = (const float*)d_in[14];
    const float* cont_w2 = (const float*)d_in[15];
    const float* cont_b2 = (const float*)d_in[16];
    const float* stats_w1 = (const float*)d_in[17];
    const float* stats_b1 = (const float*)d_in[18];
    const float* stats_w2 = (const float*)d_in[19];
    const float* stats_b2 = (const float*)d_in[20];
    const float* merge_w1 = (const float*)d_in[21];
    const float* merge_b1 = (const float*)d_in[22];
    const float* merge_w2 = (const float*)d_in[23];
    const float* merge_b2 = (const float*)d_in[24];
    float* out = (float*)d_out;

    __nv_bfloat16 *d_kw1hi, *d_cw1hi, *d_cw1lo;
    float *d_kb1p, *d_curv_h1, *d_curv, *d_cont_h1, *d_content, *d_mrg;
    cudaGetSymbolAddress((void**)&d_cw1hi, g_cw1hi);
    cudaGetSymbolAddress((void**)&d_cw1lo, g_cw1lo);
    cudaGetSymbolAddress((void**)&d_kw1hi, g_kw1hi);
    cudaGetSymbolAddress((void**)&d_kb1p, g_kb1p);
    cudaGetSymbolAddress((void**)&d_curv_h1, g_curv_h1);
    cudaGetSymbolAddress((void**)&d_curv, g_curv);
    cudaGetSymbolAddress((void**)&d_cont_h1, g_cont_h1);
    cudaGetSymbolAddress((void**)&d_content, g_content);
    cudaGetSymbolAddress((void**)&d_mrg, g_mrg);

    static cudaStream_t s1;
    static cudaEvent_t ev_conv, ev_rs, ev_s1;
    static int init_done = 0;
    if (!init_done) {
        cudaFuncSetAttribute(merge_mlp_kernel,
                             cudaFuncAttributeMaxDynamicSharedMemorySize, 113000);
        cudaFuncSetAttribute(ctx_gemm_kernel,
                             cudaFuncAttributeMaxDynamicSharedMemorySize, CTX_SMEM_BYTES);
        cudaStreamCreateWithFlags(&s1, cudaStreamNonBlocking);
        cudaEventCreateWithFlags(&ev_conv, cudaEventDisableTiming);
        cudaEventCreateWithFlags(&ev_rs,   cudaEventDisableTiming);
        cudaEventCreateWithFlags(&ev_s1,   cudaEventDisableTiming);
        init_done = 1;
    }

    int write_stats = (out_size >= BL * 64 + BL * 10) ? 1 : 0;
    int merge_smem = (128*97 + 128 + 64*130 + 64 + 32*97 + 32*130) * 4;

    // ---- main stream (default) ----
    convert_all_kernel<<<2048, 256>>>(H, cont_w1, curv_w1, curv_b1);
    cudaEventRecord(ev_conv, 0);
    mask_expand_kernel<<<BL/256, 256>>>(MASK);
    row_stats_kernel<<<BL, 256>>>(PL);
    cudaEventRecord(ev_rs, 0);
    // ncu capture slot -> ctx GEMM (full grid)
    ctx_gemm_kernel<<<dim3(LL/128, DD/128, BB), 256, CTX_SMEM_BYTES>>>();

    // ---- side stream s1: curv chain -> stats chain -> assembleA (all under ctx's shadow) ----
    cudaStreamWaitEvent(s1, ev_conv, 0);
    wmma_hilo_gemm_f32A<1,0><<<dim3(BL/128, 4), 256, 0, s1>>>(KAPPA, d_kw1hi, nullptr,
                                                              d_kb1p, d_curv_h1, 496, 248, 248);
    simt_gemm<0><<<dim3(BL/64, 1), 256, 0, s1>>>(d_curv_h1, curv_w2, curv_b2, d_curv, BL, 16, 248, 16);
    cudaStreamWaitEvent(s1, ev_rs, 0);
    stats_finalize_kernel<<<BL/256, 256, 0, s1>>>(SS, sslp_w, sslp_b, ln_g, ln_b, out, write_stats);
    stats_mlp_kernel<<<BL/32, 256, 0, s1>>>(stats_w1, stats_b1, stats_w2, stats_b2);
    content_assembleA_kernel<<<BL, 128, 0, s1>>>(H);
    cudaEventRecord(ev_s1, s1);

    // ---- main stream continues after ctx ----
    content_assembleB_kernel<<<BL, 128>>>();
    cudaStreamWaitEvent(0, ev_s1, 0);
    wmma_hilo_gemm_f32A<1,1><<<dim3(BL/128, 2), 256>>>(d_content, d_cw1hi, d_cw1lo,
                                                       cont_b1, d_cont_h1, CK, 128, 128);
    simt_gemm<0><<<dim3(BL/64, 1), 256>>>(d_cont_h1, cont_w2, cont_b2, d_mrg, BL, 64, 128, 96);
    merge_mlp_kernel<<<BL/32, 256, merge_smem>>>(merge_w1, merge_b1, merge_w2, merge_b2, out);
}

// round 16
// speedup vs baseline: 1.4142x; 1.0546x over previous
#include <cuda_runtime.h>
#include <cuda_bf16.h>
#include <mma.h>
#include <math.h>

using namespace nvcuda;

#define BB 4
#define LL 2048
#define DD 512
#define BL (BB*LL)

#define NEGV     (-10000.0f)
#define INV_TAU  (1.0f/1.5f)
#define INV_TAU_SS 0.8f
#define LOG2E    1.4426950408889634f
#define LN2      0.6931471805599453f

#define CK 1552   // content K

// ---------------- scratch (static device memory) ----------------
__device__ __nv_bfloat16 g_attn[(size_t)BL * LL];     // 33.5 MB
__device__ __nv_bfloat16 g_Hbf[(size_t)BL * DD];
__device__ float g_content[(size_t)BL * CK];
__device__ __nv_bfloat16 g_cw1hi[128*CK], g_cw1lo[128*CK];
__device__ __nv_bfloat16 g_kw1hi[256*496];            // padded N 248->256 (2-term)
__device__ float g_kb1p[256];
__device__ float g_curv_h1[(size_t)BL * 248];
__device__ float g_curv[(size_t)BL * 16];
__device__ float g_cont_h1[(size_t)BL * 128];
__device__ float g_statsin[(size_t)BL * 21];
__device__ float g_mrg[(size_t)BL * 96];
__device__ float g_pm[BL], g_mpp[BL], g_unp[BL], g_pen[BL], g_lm[BL], g_dm[BL];
__device__ int   g_ti[BL*3];
__device__ float g_twk[BL*3];
__device__ int   g_nb[BB];
__device__ unsigned char g_mask[BL];

// ---------------- helpers ----------------
__device__ inline float nan_fix(float x) {
    if (isnan(x)) return 0.0f;
    if (isinf(x)) return x > 0.0f ? 1.0f : 0.0f;
    return x;
}

__device__ inline float gelu_exact(float x) {
    return 0.5f * x * (1.0f + erff(x * 0.70710678118654752f));
}

__device__ inline unsigned ord_pack(float x) {
    unsigned u = __float_as_uint(x);
    return u ^ ((unsigned)(((int)u) >> 31) | 0x80000000u);
}
__device__ inline float ord_unpack(unsigned m) {
    unsigned u = (m & 0x80000000u) ? (m ^ 0x80000000u) : ~m;
    return __uint_as_float(u);
}

__device__ inline void cp_async16(void* smem_dst, const void* gmem_src) {
    unsigned sa = (unsigned)__cvta_generic_to_shared(smem_dst);
    asm volatile("cp.async.cg.shared.global [%0], [%1], 16;\n" :: "r"(sa), "l"(gmem_src));
}

// ---------------- H -> bf16 + all weight conversions (also zeroes g_nb) ----------------
__global__ void convert_all_kernel(const float* __restrict__ H,
                                   const float* __restrict__ cw1,
                                   const float* __restrict__ kw1,
                                   const float* __restrict__ kb1) {
    int idx = blockIdx.x * blockDim.x + threadIdx.x;
    if (blockIdx.x == 0 && threadIdx.x < BB) g_nb[threadIdx.x] = 0;

    int nH = BL * DD / 4;
    int n1 = 128 * CK;
    int n2 = 256 * 496;
    int ntot = nH + n1 + n2 + 256;

    for (; idx < ntot; idx += gridDim.x * blockDim.x) {
        if (idx < nH) {
            float4 v = ((const float4*)H)[idx];
            __nv_bfloat162 a = __floats2bfloat162_rn(v.x, v.y);
            __nv_bfloat162 b = __floats2bfloat162_rn(v.z, v.w);
            ((__nv_bfloat162*)g_Hbf)[idx*2]   = a;
            ((__nv_bfloat162*)g_Hbf)[idx*2+1] = b;
        } else if (idx < nH + n1) {
            int q = idx - nH;
            float x = cw1[q];
            __nv_bfloat16 h = __float2bfloat16(x);
            g_cw1hi[q] = h;
            g_cw1lo[q] = __float2bfloat16(x - __bfloat162float(h));
        } else if (idx < nH + n1 + n2) {
            int q = idx - nH - n1;
            float x = (q < 248*496) ? kw1[q] : 0.0f;
            g_kw1hi[q] = __float2bfloat16(x);
        } else {
            int q = idx - nH - n1 - n2;
            g_kb1p[q] = (q < 248) ? kb1[q] : 0.0f;
        }
    }
}

// ---------------- mask expand (dtype detect inline) ----------------
__global__ void mask_expand_kernel(const void* M) {
    int idx = blockIdx.x * blockDim.x + threadIdx.x;
    if (idx >= BL) return;
    unsigned int w = *(const unsigned int*)M;
    int mode;
    if      (w == 0x01010101u) mode = 0;
    else if (w == 0x3F800000u) mode = 2;
    else if (w == 0x3F803F80u) mode = 3;
    else                       mode = 1;
    unsigned char v;
    if      (mode == 0) v = ((const unsigned char*)M)[idx] != 0;
    else if (mode == 1) v = ((const int*)M)[idx] != 0;
    else if (mode == 2) v = ((const float*)M)[idx] != 0.0f;
    else                v = ((const unsigned short*)M)[idx] != 0;
    g_mask[idx] = v;
    unsigned int ball = __ballot_sync(0xffffffffu, v != 0);
    if ((idx & 31) == 0) atomicAdd(&g_nb[idx >> 11], __popc(ball));
}

// ---------------- fused row stats v3 (REDUX top-3) ----------------
__global__ __launch_bounds__(256) void row_stats_kernel(const float* __restrict__ PL)
{
    __shared__ unsigned swm[8];
    __shared__ unsigned swi[8];
    __shared__ float redf[8*3];
    __shared__ float bc[4];

    int r = blockIdx.x;
    int b = r >> 11;
    int i = r & (LL - 1);
    int tid = threadIdx.x;
    int lane = tid & 31, wid = tid >> 5;

    const float* row = PL + (size_t)r * LL;
    const unsigned char* mrow = g_mask + (size_t)b * LL;
    int Nb = g_nb[b];
    bool allv = (Nb == LL);
    bool mi = mrow[i] != 0;

    int j0 = tid * 8;
    float x[8];
    *(float4*)&x[0] = *(const float4*)&row[j0];
    *(float4*)&x[4] = *(const float4*)&row[j0 + 4];

    if (mi && allv) {
        if (i >= j0 && i < j0 + 8) x[i - j0] = NEGV;
    } else if (!mi) {
        #pragma unroll
        for (int t = 0; t < 8; t++) x[t] = NEGV;
    } else {
        #pragma unroll
        for (int t = 0; t < 8; t++) {
            int j = j0 + t;
            if (j == i || !mrow[j]) x[t] = NEGV;
        }
    }

    unsigned ou[8];
    #pragma unroll
    for (int t = 0; t < 8; t++) ou[t] = ord_pack(x[t]);

    unsigned selv[3], seli[3];
    #pragma unroll
    for (int k3 = 0; k3 < 3; k3++) {
        unsigned tm = ou[0];
        #pragma unroll
        for (int t = 1; t < 8; t++) tm = max(tm, ou[t]);
        unsigned wm = __reduce_max_sync(0xffffffffu, tm);
        if (lane == 0) swm[wid] = wm;
        __syncthreads();
        unsigned M = swm[0];
        #pragma unroll
        for (int w = 1; w < 8; w++) M = max(M, swm[w]);

        unsigned mi_idx = 0xFFFFFFFFu;
        #pragma unroll
        for (int t = 0; t < 8; t++)
            if (ou[t] == M) mi_idx = min(mi_idx, (unsigned)(j0 + t));
        unsigned wmi = __reduce_min_sync(0xffffffffu, mi_idx);
        if (lane == 0) swi[wid] = wmi;
        __syncthreads();
        unsigned I = swi[0];
        #pragma unroll
        for (int w = 1; w < 8; w++) I = min(I, swi[w]);

        selv[k3] = M; seli[k3] = I;
        if (I >= (unsigned)j0 && I < (unsigned)(j0 + 8)) ou[I - j0] = 0u;
    }

    float m = ord_unpack(selv[0]);
    float mx2 = m * (INV_TAU * LOG2E);
    float enm = exp2f(-mx2);

    float S = 0.0f, T2 = 0.0f, G = 0.0f;
    #pragma unroll
    for (int t = 0; t < 8; t++) {
        float d2 = fmaf(x[t], INV_TAU * LOG2E, -mx2);
        float e = exp2f(d2);
        S += e;
        T2 = fmaf(e, d2, T2);
        float sg = __fdividef(e, e + enm);
        G += sg;
    }
    #pragma unroll
    for (int off = 16; off >= 1; off >>= 1) {
        S  += __shfl_down_sync(0xffffffffu, S, off);
        T2 += __shfl_down_sync(0xffffffffu, T2, off);
        G  += __shfl_down_sync(0xffffffffu, G, off);
    }
    if (lane == 0) { redf[wid*3+0] = S; redf[wid*3+1] = T2; redf[wid*3+2] = G; }
    __syncthreads();
    if (wid == 0) {
        float s = 0, t2 = 0, g = 0;
        if (lane < 8) { s = redf[lane*3+0]; t2 = redf[lane*3+1]; g = redf[lane*3+2]; }
        #pragma unroll
        for (int off = 4; off >= 1; off >>= 1) {
            s  += __shfl_down_sync(0xffffffffu, s, off);
            t2 += __shfl_down_sync(0xffffffffu, t2, off);
            g  += __shfl_down_sync(0xffffffffu, g, off);
        }
        int jw = i - 8 + lane;
        float gl = 0.0f;
        if (lane < 17 && jw >= 0 && jw < LL) {
            float xw = row[jw];
            bool valid = mi && (jw != i) && (allv || mrow[jw]);
            if (!valid) xw = NEGV;
            float d2 = fmaf(xw, INV_TAU * LOG2E, -mx2);
            float e = exp2f(d2);
            gl = __fdividef(e, e + enm);
        }
        #pragma unroll
        for (int off = 16; off >= 1; off >>= 1)
            gl += __shfl_down_sync(0xffffffffu, gl, off);
        if (lane == 0) { bc[0] = s; bc[1] = t2; bc[2] = g; bc[3] = gl; }
    }
    __syncthreads();

    float St = bc[0];
    float invS = __fdividef(1.0f, St);

    __nv_bfloat162 ob[4];
    #pragma unroll
    for (int p = 0; p < 4; p++) {
        float e0 = exp2f(fmaf(x[2*p],   INV_TAU * LOG2E, -mx2));
        float e1 = exp2f(fmaf(x[2*p+1], INV_TAU * LOG2E, -mx2));
        ob[p] = __floats2bfloat162_rn(e0 * invS, e1 * invS);
    }
    *(uint4*)&g_attn[(size_t)r * LL + j0] = *(uint4*)ob;

    if (tid == 0) {
        float Tt = bc[1] * LN2;
        float Gt = bc[2];
        float Glt = bc[3];

        int lo = i - 8 < 0 ? 0 : i - 8;
        int hi = i + 8 > LL-1 ? LL-1 : i + 8;
        float wcount;
        if (allv) wcount = (float)(hi - lo + 1);
        else { int c = 0; for (int j = lo; j <= hi; j++) c += mrow[j]; wcount = (float)c; }
        float nvalid  = mi ? (float)(Nb - 1) : 0.0f;
        float nlocal  = mi ? (wcount - 1.0f) : 0.0f;
        float ndistal = nvalid - nlocal;

        float entropy = logf(St) - Tt / St;
        float maxpp = __fdividef(1.0f, 1.0f + enm);
        float pen = entropy / fmaxf(logf(fmaxf(nvalid, 1.0f)), 1e-4f);
        pen = fminf(fmaxf(pen, 0.0f), 1.0f);

        g_pm[r]  = __fdividef(Gt, fmaxf(nvalid, 1.0f));
        g_mpp[r] = maxpp;
        g_unp[r] = 1.0f - maxpp;
        g_pen[r] = nan_fix(pen);
        g_lm[r]  = __fdividef(Glt, fmaxf(nlocal, 1.0f));
        g_dm[r]  = __fdividef(Gt - Glt, fmaxf(ndistal, 1.0f));

        float tvv[3] = {ord_unpack(selv[0]), ord_unpack(selv[1]), ord_unpack(selv[2])};
        float mt = (tvv[0] > -9000.0f) ? tvv[0] : NEGV;
        float a[3]; float ssum = 0.0f;
        #pragma unroll
        for (int k = 0; k < 3; k++) {
            bool val = tvv[k] > -9000.0f;
            a[k] = val ? __expf((tvv[k] - mt) * INV_TAU) : 0.0f;
            ssum += a[k];
        }
        float inv = __fdividef(1.0f, fmaxf(ssum, 1e-8f));
        #pragma unroll
        for (int k = 0; k < 3; k++) {
            g_twk[r*3+k] = a[k] * inv;
            g_ti[r*3+k]  = (int)seli[k];
        }
    }
}

// ---------------- ctx = attn @ H (wmma, 3-stage, R9 scheme), writes content cols 512-1023 ----------------
#define CTX_STAGE_A (128*40)
#define CTX_STAGE_B (32*136)
#define CTX_STAGE_ELEMS (CTX_STAGE_A + CTX_STAGE_B)
#define CTX_SMEM_BYTES (3 * CTX_STAGE_ELEMS * 2)

__global__ __launch_bounds__(256, 2) void ctx_gemm_kernel() {
    extern __shared__ __align__(16) __nv_bfloat16 smem_ctx[];
    __nv_bfloat16* As[3];
    __nv_bfloat16* Bs[3];
    #pragma unroll
    for (int s = 0; s < 3; s++) {
        As[s] = smem_ctx + s * CTX_STAGE_ELEMS;
        Bs[s] = As[s] + CTX_STAGE_A;
    }

    int m0 = blockIdx.x * 128;
    int n0 = blockIdx.y * 128;
    int b  = blockIdx.z;
    const __nv_bfloat16* A  = g_attn + (size_t)b * LL * LL;
    const __nv_bfloat16* Bm = g_Hbf  + (size_t)b * LL * DD;
    float* C = g_content + (size_t)b * LL * CK + 512;   // ctx block of content_in

    int tid = threadIdx.x;
    int wid = tid >> 5;
    int wm = wid & 3;
    int wn = wid >> 2;

    wmma::fragment<wmma::accumulator, 16, 16, 16, float> acc[2][4];
    #pragma unroll
    for (int x = 0; x < 2; x++)
        #pragma unroll
        for (int y = 0; y < 4; y++)
            wmma::fill_fragment(acc[x][y], 0.0f);

    auto load_stage = [&](int st, int k0) {
        #pragma unroll
        for (int it = 0; it < 2; it++) {
            int q = tid + it * 256;
            int rowA = q >> 2, c4 = q & 3;
            cp_async16(&As[st][rowA * 40 + c4 * 8],
                       &A[(size_t)(m0 + rowA) * LL + k0 + c4 * 8]);
            int rowB = q >> 4, c16 = q & 15;
            cp_async16(&Bs[st][rowB * 136 + c16 * 8],
                       &Bm[(size_t)(k0 + rowB) * DD + n0 + c16 * 8]);
        }
        asm volatile("cp.async.commit_group;\n" ::: "memory");
    };

    load_stage(0, 0);
    load_stage(1, 32);
    load_stage(2, 64);

    for (int c = 0; c < 64; c++) {
        int st = c % 3;
        if (c < 62) asm volatile("cp.async.wait_group 2;\n" ::: "memory");
        else        asm volatile("cp.async.wait_group 0;\n" ::: "memory");
        __syncthreads();
        #pragma unroll
        for (int kk = 0; kk < 32; kk += 16) {
            wmma::fragment<wmma::matrix_a, 16, 16, 16, __nv_bfloat16, wmma::row_major> af[2];
            wmma::fragment<wmma::matrix_b, 16, 16, 16, __nv_bfloat16, wmma::row_major> bf[4];
            #pragma unroll
            for (int x = 0; x < 2; x++)
                wmma::load_matrix_sync(af[x], &As[st][(wm*32 + x*16) * 40 + kk], 40);
            #pragma unroll
            for (int y = 0; y < 4; y++)
                wmma::load_matrix_sync(bf[y], &Bs[st][kk * 136 + wn*64 + y*16], 136);
            #pragma unroll
            for (int x = 0; x < 2; x++)
                #pragma unroll
                for (int y = 0; y < 4; y++)
                    wmma::mma_sync(acc[x][y], af[x], bf[y], acc[x][y]);
        }
        __syncthreads();
        if (c + 3 < 64) load_stage(st, (c + 3) * 32);
    }

    #pragma unroll
    for (int x = 0; x < 2; x++)
        #pragma unroll
        for (int y = 0; y < 4; y++)
            wmma::store_matrix_sync(
                C + (size_t)(m0 + wm*32 + x*16) * CK + n0 + wn*64 + y*16,
                acc[x][y], CK, wmma::mem_row_major);
}

// ---------------- hi/lo bf16 tensor-core GEMM, fp32 A split in-kernel ----------------
template<int ACT, int PREC>
__global__ __launch_bounds__(256) void wmma_hilo_gemm_f32A(
    const float* __restrict__ A,
    const __nv_bfloat16* __restrict__ Whi, const __nv_bfloat16* __restrict__ Wlo,
    const float* __restrict__ bias, float* __restrict__ C,
    int K, int Nout, int ldc)
{
    __shared__ __align__(16) char sraw[35840];
    __nv_bfloat16* sAhi = (__nv_bfloat16*)sraw;
    __nv_bfloat16* sAlo = sAhi + 128*40;
    __nv_bfloat16* sWhi = sAlo + 128*40;
    __nv_bfloat16* sWlo = sWhi + 64*40;
    float* stage = (float*)sraw;

    int m0 = blockIdx.x * 128;
    int n0 = blockIdx.y * 64;
    int tid = threadIdx.x, wid = tid >> 5;
    int wm = wid & 3, wn = wid >> 2;

    wmma::fragment<wmma::accumulator, 16, 16, 16, float> acc[2][2];
    #pragma unroll
    for (int x = 0; x < 2; x++)
        #pragma unroll
        for (int y = 0; y < 2; y++)
            wmma::fill_fragment(acc[x][y], 0.0f);

    int Kpad = (K + 31) & ~31;
    for (int k0 = 0; k0 < Kpad; k0 += 32) {
        #pragma unroll
        for (int it = 0; it < 4; it++) {
            int q = tid + it * 256;
            int rowA = q >> 3, c = q & 7;
            int kidx = k0 + c * 4;
            float4 v = make_float4(0.f, 0.f, 0.f, 0.f);
            if (kidx < K)
                v = *(const float4*)&A[(size_t)(m0 + rowA) * K + kidx];
            float xs[4] = {v.x, v.y, v.z, v.w};
            #pragma unroll
            for (int u = 0; u < 4; u++) {
                __nv_bfloat16 h = __float2bfloat16(xs[u]);
                sAhi[rowA*40 + c*4 + u] = h;
                sAlo[rowA*40 + c*4 + u] = __float2bfloat16(xs[u] - __bfloat162float(h));
            }
        }
        {
            int rowN = tid >> 2, c4 = tid & 3;
            int kidx = k0 + c4 * 8;
            uint4 vh = make_uint4(0,0,0,0), vl = make_uint4(0,0,0,0);
            if (kidx < K) {
                vh = *(const uint4*)&Whi[(size_t)(n0 + rowN) * K + kidx];
                if (PREC) vl = *(const uint4*)&Wlo[(size_t)(n0 + rowN) * K + kidx];
            }
            *(uint4*)&sWhi[rowN * 40 + c4 * 8] = vh;
            if (PREC) *(uint4*)&sWlo[rowN * 40 + c4 * 8] = vl;
        }
        __syncthreads();
        #pragma unroll
        for (int kk = 0; kk < 32; kk += 16) {
            wmma::fragment<wmma::matrix_a, 16, 16, 16, __nv_bfloat16, wmma::row_major> ah[2], al[2];
            wmma::fragment<wmma::matrix_b, 16, 16, 16, __nv_bfloat16, wmma::col_major> bh[2], bl[2];
            #pragma unroll
            for (int x = 0; x < 2; x++) {
                wmma::load_matrix_sync(ah[x], &sAhi[(wm*32 + x*16) * 40 + kk], 40);
                wmma::load_matrix_sync(al[x], &sAlo[(wm*32 + x*16) * 40 + kk], 40);
            }
            #pragma unroll
            for (int y = 0; y < 2; y++) {
                wmma::load_matrix_sync(bh[y], &sWhi[(wn*32 + y*16) * 40 + kk], 40);
                if (PREC) wmma::load_matrix_sync(bl[y], &sWlo[(wn*32 + y*16) * 40 + kk], 40);
            }
            #pragma unroll
            for (int x = 0; x < 2; x++)
                #pragma unroll
                for (int y = 0; y < 2; y++) {
                    wmma::mma_sync(acc[x][y], ah[x], bh[y], acc[x][y]);
                    if (PREC) wmma::mma_sync(acc[x][y], ah[x], bl[y], acc[x][y]);
                    wmma::mma_sync(acc[x][y], al[x], bh[y], acc[x][y]);
                }
        }
        __syncthreads();
    }

    #pragma unroll
    for (int x = 0; x < 2; x++)
        #pragma unroll
        for (int y = 0; y < 2; y++)
            wmma::store_matrix_sync(&stage[(wm*32 + x*16) * 68 + wn*32 + y*16],
                                    acc[x][y], 68, wmma::mem_row_major);
    __syncthreads();
    #pragma unroll
    for (int t = 0; t < 32; t++) {
        int q = tid + t * 256;
        int rowm = q >> 6, col = q & 63;
        int n = n0 + col;
        if (n < Nout) {
            float c = stage[rowm * 68 + col] + bias[n];
            if (ACT == 1) c = gelu_exact(c);
            C[(size_t)(m0 + rowm) * ldc + n] = c;
        }
    }
}

// ---------------- SIMT fp32 GEMM (small layers) ----------------
template<int ACT>
__global__ __launch_bounds__(256) void simt_gemm(
    const float* __restrict__ A, const float* __restrict__ W,
    const float* __restrict__ bias, float* __restrict__ C,
    int M, int N, int K, int ldc)
{
    __shared__ __align__(16) float As[16][68];
    __shared__ __align__(16) float Ws[16][68];
    int m0 = blockIdx.x * 64;
    int n0 = blockIdx.y * 64;
    int tid = threadIdx.x;
    int tr = tid & 15, tc = tid >> 4;

    float acc[4][4] = {};

    for (int k0 = 0; k0 < K; k0 += 16) {
        #pragma unroll
        for (int it = 0; it < 4; it++) {
            int q = tid + it * 256;
            int m = q >> 4, k = q & 15;
            As[k][m] = (k0 + k < K) ? A[(size_t)(m0 + m) * K + k0 + k] : 0.0f;
            int n = m;
            Ws[k][n] = (n0 + n < N && k0 + k < K) ? W[(size_t)(n0 + n) * K + k0 + k] : 0.0f;
        }
        __syncthreads();
        #pragma unroll
        for (int kk = 0; kk < 16; kk++) {
            float4 av = *(const float4*)&As[kk][tr * 4];
            float4 wv = *(const float4*)&Ws[kk][tc * 4];
            float a4[4] = {av.x, av.y, av.z, av.w};
            float w4[4] = {wv.x, wv.y, wv.z, wv.w};
            #pragma unroll
            for (int x = 0; x < 4; x++)
                #pragma unroll
                for (int y = 0; y < 4; y++)
                    acc[x][y] += a4[x] * w4[y];
        }
        __syncthreads();
    }

    #pragma unroll
    for (int x = 0; x < 4; x++) {
        int m = m0 + tr * 4 + x;
        #pragma unroll
        for (int y = 0; y < 4; y++) {
            int n = n0 + tc * 4 + y;
            if (n < N) {
                float c = acc[x][y] + bias[n];
                if (ACT == 1) c = gelu_exact(c);
                C[(size_t)m * ldc + n] = c;
            }
        }
    }
}

// ---------------- stats finalize + layernorm + ss ----------------
__global__ void stats_finalize_kernel(
    const float* __restrict__ SS,
    const float* __restrict__ sslp_w, const float* __restrict__ sslp_b,
    const float* __restrict__ ln_g, const float* __restrict__ ln_b,
    float* __restrict__ out, int write_stats)
{
    int r = blockIdx.x * blockDim.x + threadIdx.x;
    if (r >= BL) return;
    int b = r >> 11;
    int i = r & (LL - 1);
    const unsigned char* mrow = g_mask + (size_t)b * LL;
    float mf = mrow[i] ? 1.0f : 0.0f;

    const float* s = SS + (size_t)r * 3;
    float s0 = s[0], s1 = s[1], s2 = s[2];
    float t0 = s0 * INV_TAU_SS, t1 = s1 * INV_TAU_SS, t2 = s2 * INV_TAU_SS;
    float mss = fmaxf(t0, fmaxf(t1, t2));
    float e0 = __expf(t0 - mss), e1 = __expf(t1 - mss), e2 = __expf(t2 - mss);
    float es = e0 + e1 + e2;
    float p0 = e0 / es, p1 = e1 / es, p2 = e2 / es;
    float ssent = -(p0 * logf(p0 + 1e-8f) + p1 * logf(p1 + 1e-8f) + p2 * logf(p2 + 1e-8f));

    float sx3 = 0, sm3 = 0, sx7 = 0, sm7 = 0, se7 = 0;
    for (int d = -5; d <= 5; d++) {
        int j = i + d;
        if (j < 0 || j >= LL) continue;
        float mfj = mrow[j] ? 1.0f : 0.0f;
        int rj = b * LL + j;
        float u = g_unp[rj] * mfj;
        float p = g_pen[rj] * mfj;
        if (d >= -2 && d <= 2) { sx3 += u; sm3 += mfj; }
        sx7 += u; sm7 += mfj; se7 += p;
    }
    float w3 = sx3 / fmaxf(sm3, 1.0f);
    float w7 = sx7 / fmaxf(sm7, 1.0f);
    float e7 = se7 / fmaxf(sm7, 1.0f);

    float st[10];
    st[0] = g_pm[r]; st[1] = g_mpp[r]; st[2] = g_unp[r]; st[3] = g_pen[r];
    st[4] = ssent;   st[5] = g_lm[r];  st[6] = g_dm[r];
    st[7] = w3; st[8] = w7; st[9] = e7;
    #pragma unroll
    for (int c = 0; c < 10; c++) st[c] = nan_fix(st[c] * mf);

    if (write_stats) {
        float* os = out + (size_t)BL * 64 + (size_t)r * 10;
        #pragma unroll
        for (int c = 0; c < 10; c++) os[c] = st[c];
    }

    float mean = 0;
    #pragma unroll
    for (int c = 0; c < 10; c++) mean += st[c];
    mean *= 0.1f;
    float var = 0;
    #pragma unroll
    for (int c = 0; c < 10; c++) { float d = st[c] - mean; var += d * d; }
    var *= 0.1f;
    float rstd = rsqrtf(var + 1e-5f);

    float* si = g_statsin + (size_t)r * 21;
    #pragma unroll
    for (int c = 0; c < 10; c++) si[c] = (st[c] - mean) * rstd * ln_g[c] + ln_b[c];
    si[10] = p0; si[11] = p1; si[12] = p2;
    #pragma unroll
    for (int o = 0; o < 8; o++)
        si[13 + o] = sslp_w[o*3+0] * s0 + sslp_w[o*3+1] * s1 + sslp_w[o*3+2] * s2 + sslp_b[o];
}

// ---------------- content assembly A: H, topk, curv (cols 0-511, 1024-1551) ----------------
__global__ void content_assembleA_kernel(const float* __restrict__ H) {
    int r = blockIdx.x;
    int b = r >> 11;
    int tid = threadIdx.x;

    int   i0 = g_ti[r*3+0], i1 = g_ti[r*3+1], i2 = g_ti[r*3+2];
    float w0 = g_twk[r*3+0], w1 = g_twk[r*3+1], w2 = g_twk[r*3+2];
    const float* Hb = H + (size_t)b * LL * DD;
    const float* Hr = H + (size_t)r * DD;
    float* dst = g_content + (size_t)r * CK;

    for (int d = tid; d < DD; d += 128) {
        dst[d] = Hr[d];
        float ct = 0.0f;
        if (i0 >= 0) ct += w0 * Hb[(size_t)i0 * DD + d];
        if (i1 >= 0) ct += w1 * Hb[(size_t)i1 * DD + d];
        if (i2 >= 0) ct += w2 * Hb[(size_t)i2 * DD + d];
        dst[1024 + d] = ct;
    }
    if (tid < 16) dst[1536 + tid] = g_curv[(size_t)r * 16 + tid];
}

// ---------------- fused stats MLP: 21 -> 64 (gelu) -> 32 ----------------
__global__ __launch_bounds__(256) void stats_mlp_kernel(
    const float* __restrict__ W1, const float* __restrict__ B1,
    const float* __restrict__ W2, const float* __restrict__ B2)
{
    __shared__ float sw1[64*22], sb1[64], sw2[32*66], sb2[32];
    __shared__ float sin_[32*22];
    __shared__ float sh[32*66];
    int r0 = blockIdx.x * 32;
    int tid = threadIdx.x;

    for (int q = tid; q < 64*21; q += 256) { int n = q/21, k = q%21; sw1[n*22+k] = W1[q]; }
    for (int q = tid; q < 32*64; q += 256) { int n = q/64, k = q%64; sw2[n*66+k] = W2[q]; }
    if (tid < 64) sb1[tid] = B1[tid];
    if (tid < 32) sb2[tid] = B2[tid];
    for (int q = tid; q < 32*21; q += 256) {
        int rr = q/21, k = q%21;
        sin_[rr*22+k] = g_statsin[(size_t)(r0+rr)*21 + k];
    }
    __syncthreads();

    int row = tid >> 3;
    #pragma unroll
    for (int j = 0; j < 8; j++) {
        int col = (tid & 7) + 8*j;
        float acc = sb1[col];
        #pragma unroll
        for (int k = 0; k < 21; k++) acc = fmaf(sin_[row*22+k], sw1[col*22+k], acc);
        sh[row*66+col] = gelu_exact(acc);
    }
    __syncthreads();
    #pragma unroll
    for (int j = 0; j < 4; j++) {
        int col = (tid & 7) + 8*j;
        float acc = sb2[col];
        #pragma unroll
        for (int k = 0; k < 64; k++) acc = fmaf(sh[row*66+k], sw2[col*66+k], acc);
        g_mrg[(size_t)(r0+row)*96 + 64 + col] = acc;
    }
}

// ---------------- fused merge MLP: 96 -> 128 (gelu) -> 64, masked ----------------
__global__ __launch_bounds__(256) void merge_mlp_kernel(
    const float* __restrict__ W1, const float* __restrict__ B1,
    const float* __restrict__ W2, const float* __restrict__ B2,
    float* __restrict__ out)
{
    extern __shared__ float dy[];
    float* sw1 = dy;
    float* sb1 = sw1 + 128*97;
    float* sw2 = sb1 + 128;
    float* sb2 = sw2 + 64*130;
    float* sin_ = sb2 + 64;
    float* sh  = sin_ + 32*97;

    int r0 = blockIdx.x * 32;
    int tid = threadIdx.x;

    for (int q = tid; q < 128*96; q += 256) { int n = q/96, k = q%96; sw1[n*97+k] = W1[q]; }
    for (int q = tid; q < 64*128; q += 256) { int n = q/128, k = q%128; sw2[n*130+k] = W2[q]; }
    if (tid < 128) sb1[tid] = B1[tid];
    if (tid < 64)  sb2[tid] = B2[tid];
    for (int q = tid; q < 32*96; q += 256) {
        int rr = q/96, k = q%96;
        sin_[rr*97+k] = g_mrg[(size_t)(r0+rr)*96 + k];
    }
    __syncthreads();

    int row = tid >> 3;
    #pragma unroll
    for (int j = 0; j < 16; j++) {
        int col = (tid & 7) + 8*j;
        float acc = sb1[col];
        #pragma unroll 8
        for (int k = 0; k < 96; k++) acc = fmaf(sin_[row*97+k], sw1[col*97+k], acc);
        sh[row*130+col] = gelu_exact(acc);
    }
    __syncthreads();
    float mf = g_mask[r0 + row] ? 1.0f : 0.0f;
    #pragma unroll
    for (int j = 0; j < 8; j++) {
        int col = (tid & 7) + 8*j;
        float acc = sb2[col];
        #pragma unroll 8
        for (int k = 0; k < 128; k++) acc = fmaf(sh[row*130+k], sw2[col*130+k], acc);
        out[(size_t)(r0+row)*64 + col] = acc * mf;
    }
}

// ---------------- host launch ----------------
extern "C" void kernel_launch(void* const* d_in, const int* in_sizes, int n_in,
                              void* d_out, int out_size) {
    const float* H      = (const float*)d_in[0];
    const float* PL     = (const float*)d_in[1];
    const float* SS     = (const float*)d_in[2];
    const float* KAPPA  = (const float*)d_in[3];
    const void*  MASK   = (const void*)d_in[4];
    const float* curv_w1 = (const float*)d_in[5];
    const float* curv_b1 = (const float*)d_in[6];
    const float* curv_w2 = (const float*)d_in[7];
    const float* curv_b2 = (const float*)d_in[8];
    const float* sslp_w  = (const float*)d_in[9];
    const float* sslp_b  = (const float*)d_in[10];
    const float* ln_g    = (const float*)d_in[11];
    const float* ln_b    = (const float*)d_in[12];
    const float* cont_w1 = (const float*)d_in[13];
    const float* cont_b1 = (const float*)d_in[14];
    const float* cont_w2 = (const float*)d_in[15];
    const float* cont_b2 = (const float*)d_in[16];
    const float* stats_w1 = (const float*)d_in[17];
    const float* stats_b1 = (const float*)d_in[18];
    const float* stats_w2 = (const float*)d_in[19];
    const float* stats_b2 = (const float*)d_in[20];
    const float* merge_w1 = (const float*)d_in[21];
    const float* merge_b1 = (const float*)d_in[22];
    const float* merge_w2 = (const float*)d_in[23];
    const float* merge_b2 = (const float*)d_in[24];
    float* out = (float*)d_out;

    __nv_bfloat16 *d_kw1hi, *d_cw1hi, *d_cw1lo;
    float *d_kb1p, *d_curv_h1, *d_curv, *d_cont_h1, *d_content, *d_mrg;
    cudaGetSymbolAddress((void**)&d_cw1hi, g_cw1hi);
    cudaGetSymbolAddress((void**)&d_cw1lo, g_cw1lo);
    cudaGetSymbolAddress((void**)&d_kw1hi, g_kw1hi);
    cudaGetSymbolAddress((void**)&d_kb1p, g_kb1p);
    cudaGetSymbolAddress((void**)&d_curv_h1, g_curv_h1);
    cudaGetSymbolAddress((void**)&d_curv, g_curv);
    cudaGetSymbolAddress((void**)&d_cont_h1, g_cont_h1);
    cudaGetSymbolAddress((void**)&d_content, g_content);
    cudaGetSymbolAddress((void**)&d_mrg, g_mrg);

    static cudaStream_t s1;
    static cudaEvent_t ev_conv, ev_rs, ev_aA, ev_stats;
    static int init_done = 0;
    if (!init_done) {
        cudaFuncSetAttribute(merge_mlp_kernel,
                             cudaFuncAttributeMaxDynamicSharedMemorySize, 113000);
        cudaFuncSetAttribute(ctx_gemm_kernel,
                             cudaFuncAttributeMaxDynamicSharedMemorySize, CTX_SMEM_BYTES);
        cudaStreamCreateWithFlags(&s1, cudaStreamNonBlocking);
        cudaEventCreateWithFlags(&ev_conv,  cudaEventDisableTiming);
        cudaEventCreateWithFlags(&ev_rs,    cudaEventDisableTiming);
        cudaEventCreateWithFlags(&ev_aA,    cudaEventDisableTiming);
        cudaEventCreateWithFlags(&ev_stats, cudaEventDisableTiming);
        init_done = 1;
    }

    int write_stats = (out_size >= BL * 64 + BL * 10) ? 1 : 0;
    int merge_smem = (128*97 + 128 + 64*130 + 64 + 32*97 + 32*130) * 4;

    // ---- main stream (default) ----
    convert_all_kernel<<<2048, 256>>>(H, cont_w1, curv_w1, curv_b1);
    cudaEventRecord(ev_conv, 0);
    mask_expand_kernel<<<BL/256, 256>>>(MASK);
    row_stats_kernel<<<BL, 256>>>(PL);
    cudaEventRecord(ev_rs, 0);
    // ncu capture slot -> ctx GEMM (writes content cols 512-1023 directly)
    ctx_gemm_kernel<<<dim3(LL/128, DD/128, BB), 256, CTX_SMEM_BYTES>>>();

    // ---- side stream s1: curv -> assembleA (critical) -> stats (merge-only) ----
    cudaStreamWaitEvent(s1, ev_conv, 0);
    wmma_hilo_gemm_f32A<1,0><<<dim3(BL/128, 4), 256, 0, s1>>>(KAPPA, d_kw1hi, nullptr,
                                                              d_kb1p, d_curv_h1, 496, 248, 248);
    simt_gemm<0><<<dim3(BL/64, 1), 256, 0, s1>>>(d_curv_h1, curv_w2, curv_b2, d_curv, BL, 16, 248, 16);
    cudaStreamWaitEvent(s1, ev_rs, 0);
    content_assembleA_kernel<<<BL, 128, 0, s1>>>(H);
    cudaEventRecord(ev_aA, s1);
    stats_finalize_kernel<<<BL/256, 256, 0, s1>>>(SS, sslp_w, sslp_b, ln_g, ln_b, out, write_stats);
    stats_mlp_kernel<<<BL/32, 256, 0, s1>>>(stats_w1, stats_b1, stats_w2, stats_b2);
    cudaEventRecord(ev_stats, s1);

    // ---- main stream continues after ctx + assembleA ----
    cudaStreamWaitEvent(0, ev_aA, 0);
    wmma_hilo_gemm_f32A<1,1><<<dim3(BL/128, 2), 256>>>(d_content, d_cw1hi, d_cw1lo,
                                                       cont_b1, d_cont_h1, CK, 128, 128);
    simt_gemm<0><<<dim3(BL/64, 1), 256>>>(d_cont_h1, cont_w2, cont_b2, d_mrg, BL, 64, 128, 96);
    cudaStreamWaitEvent(0, ev_stats, 0);
    merge_mlp_kernel<<<BL/32, 256, merge_smem>>>(merge_w1, merge_b1, merge_w2, merge_b2, out);
}